// round 1
// baseline (speedup 1.0000x reference)
#include <cuda_runtime.h>
#include <math.h>
#include <stdint.h>

// Problem constants
#define BATCH   4
#define SEQ     2048
#define DMODEL  1024
#define DINNER  2048
#define DSTATE  16
#define DTRANK  64
#define DCONV   4
#define MROWS   (BATCH*SEQ)          // 8192
#define NXZ     (2*DINNER)           // 4096
#define NDBL    (DTRANK + 2*DSTATE)  // 96

// ----------------------------------------------------------------------------
// Scratch (device globals; no runtime allocation allowed)
// ----------------------------------------------------------------------------
__device__ float g_xz [(size_t)MROWS * NXZ];     // in_proj output (x_ssm | z)
__device__ float g_xc [(size_t)MROWS * DINNER];  // conv+silu output
__device__ float g_dbl[(size_t)MROWS * NDBL];    // x_proj output (dt_x | B | C)
__device__ float g_dt [(size_t)MROWS * DINNER];  // softplus(dt)
__device__ float g_y  [(size_t)MROWS * DINNER];  // gated scan output

// ----------------------------------------------------------------------------
// Generic NT SGEMM: C[M,N] = A[M,K] * B[N,K]^T  (+ optional softplus(bias) epi)
// Register-prefetch double buffering of the global->smem path.
// EPI: 0 = none, 1 = softplus(acc + bias[col])
// ----------------------------------------------------------------------------
template<int BM, int BN, int BK, int TM, int TN, int EPI>
__global__ void __launch_bounds__((BM/TM)*(BN/TN))
sgemm_nt(const float* __restrict__ A, const float* __restrict__ B,
         float* __restrict__ C, const float* __restrict__ bias,
         int M, int N, int K, int lda, int ldb, int ldc)
{
    constexpr int NT = (BM/TM)*(BN/TN);
    constexpr int TX = BN/TN;
    constexpr int KV = BK/4;
    static_assert(NT == 256, "expect 256 threads");

    __shared__ float As[BK][BM];
    __shared__ float Bs[BK][BN];

    const int tid = threadIdx.x;
    const int tx  = tid % TX;
    const int ty  = tid / TX;
    const int rowBase = blockIdx.y * BM;
    const int colBase = blockIdx.x * BN;

    // Per-thread global-load coordinates (one float4 each, maybe predicated)
    const int  aRow = tid / KV;
    const int  aK   = (tid % KV) * 4;
    const bool aVal = (tid < BM*KV);
    const int  bRow = tid / KV;
    const int  bK   = (tid % KV) * 4;
    const bool bVal = (tid < BN*KV);

    const int nk = K / BK;

    float acc[TM][TN];
#pragma unroll
    for (int i = 0; i < TM; ++i)
#pragma unroll
        for (int j = 0; j < TN; ++j) acc[i][j] = 0.f;

    float4 aReg = make_float4(0,0,0,0);
    float4 bReg = make_float4(0,0,0,0);

    // ---- load tile 0
    if (aVal) {
        int gr = rowBase + aRow;
        if (gr < M) aReg = *reinterpret_cast<const float4*>(&A[(size_t)gr*lda + aK]);
    }
    if (bVal) {
        int gr = colBase + bRow;
        if (gr < N) bReg = *reinterpret_cast<const float4*>(&B[(size_t)gr*ldb + bK]);
        else        bReg = make_float4(0,0,0,0);
    }
    if (aVal) {
        As[aK+0][aRow] = aReg.x; As[aK+1][aRow] = aReg.y;
        As[aK+2][aRow] = aReg.z; As[aK+3][aRow] = aReg.w;
    }
    if (bVal) {
        Bs[bK+0][bRow] = bReg.x; Bs[bK+1][bRow] = bReg.y;
        Bs[bK+2][bRow] = bReg.z; Bs[bK+3][bRow] = bReg.w;
    }
    __syncthreads();

    for (int kt = 0; kt < nk; ++kt) {
        // prefetch next tile into registers while computing current
        if (kt + 1 < nk) {
            const int ko = (kt+1)*BK;
            if (aVal) {
                int gr = rowBase + aRow;
                aReg = (gr < M) ? *reinterpret_cast<const float4*>(&A[(size_t)gr*lda + ko + aK])
                                : make_float4(0,0,0,0);
            }
            if (bVal) {
                int gr = colBase + bRow;
                bReg = (gr < N) ? *reinterpret_cast<const float4*>(&B[(size_t)gr*ldb + ko + bK])
                                : make_float4(0,0,0,0);
            }
        }

#pragma unroll
        for (int kk = 0; kk < BK; ++kk) {
            float ra[TM], rb[TN];
#pragma unroll
            for (int i = 0; i < TM; i += 4)
                *reinterpret_cast<float4*>(&ra[i]) =
                    *reinterpret_cast<const float4*>(&As[kk][ty*TM + i]);
#pragma unroll
            for (int j = 0; j < TN; j += 4)
                *reinterpret_cast<float4*>(&rb[j]) =
                    *reinterpret_cast<const float4*>(&Bs[kk][tx*TN + j]);
#pragma unroll
            for (int i = 0; i < TM; ++i)
#pragma unroll
                for (int j = 0; j < TN; ++j)
                    acc[i][j] = fmaf(ra[i], rb[j], acc[i][j]);
        }
        __syncthreads();
        if (kt + 1 < nk) {
            if (aVal) {
                As[aK+0][aRow] = aReg.x; As[aK+1][aRow] = aReg.y;
                As[aK+2][aRow] = aReg.z; As[aK+3][aRow] = aReg.w;
            }
            if (bVal) {
                Bs[bK+0][bRow] = bReg.x; Bs[bK+1][bRow] = bReg.y;
                Bs[bK+2][bRow] = bReg.z; Bs[bK+3][bRow] = bReg.w;
            }
            __syncthreads();
        }
    }

    // ---- epilogue
#pragma unroll
    for (int i = 0; i < TM; ++i) {
        int r = rowBase + ty*TM + i;
        if (r >= M) continue;
#pragma unroll
        for (int j = 0; j < TN; ++j) {
            int c = colBase + tx*TN + j;
            if (c >= N) continue;
            float v = acc[i][j];
            if (EPI == 1) {
                v += bias[c];
                // stable softplus
                v = fmaxf(v, 0.f) + log1pf(__expf(-fabsf(v)));
            }
            C[(size_t)r*ldc + c] = v;
        }
    }
}

// ----------------------------------------------------------------------------
// Depthwise causal conv (width 4) + SiLU, reading x_ssm half of xz
// ----------------------------------------------------------------------------
__global__ void conv_silu_kernel(const float* __restrict__ xz,
                                 const float* __restrict__ w,
                                 const float* __restrict__ b,
                                 float* __restrict__ xc)
{
    int idx = blockIdx.x * blockDim.x + threadIdx.x;   // over MROWS*DINNER
    int d = idx & (DINNER - 1);
    int m = idx >> 11;                                  // DINNER = 2048 = 2^11
    int l = m & (SEQ - 1);

    float acc = b[d];
#pragma unroll
    for (int j = 0; j < DCONV; ++j) {
        int lj = l - (DCONV - 1) + j;
        if (lj >= 0)
            acc = fmaf(w[d*DCONV + j], xz[(size_t)(m - (DCONV-1) + j) * NXZ + d], acc);
    }
    xc[(size_t)idx] = acc / (1.f + __expf(-acc));       // silu
}

// ----------------------------------------------------------------------------
// Selective scan: one lane per (channel d, state n). 16 lanes per channel,
// 2 channels per warp, 8 warps per block -> 16 channels / block.
// Fuses  y = (scan + D*x) * silu(z).
// ----------------------------------------------------------------------------
__global__ void __launch_bounds__(256) scan_kernel(
    const float* __restrict__ dt,  const float* __restrict__ dbl,
    const float* __restrict__ xc,  const float* __restrict__ xz,
    const float* __restrict__ A_log, const float* __restrict__ Dp,
    float* __restrict__ y)
{
    const int lane = threadIdx.x & 31;
    const int warp = threadIdx.x >> 5;
    const int n    = lane & 15;
    const int d    = blockIdx.x * 16 + warp * 2 + (lane >> 4);
    const int b    = blockIdx.y;

    const float Ad = -__expf(A_log[d*DSTATE + n]);
    const float Dd = Dp[d];
    float h = 0.f;

    const int m0 = b * SEQ;
    for (int l = 0; l < SEQ; ++l) {
        const int m = m0 + l;
        const float dtv = dt [(size_t)m*DINNER + d];
        const float xv  = xc [(size_t)m*DINNER + d];
        const float Bv  = dbl[m*NDBL + DTRANK + n];
        const float Cv  = dbl[m*NDBL + DTRANK + DSTATE + n];

        const float dA = __expf(dtv * Ad);
        h = fmaf(dA, h, dtv * Bv * xv);

        float p = h * Cv;
        p += __shfl_xor_sync(0xffffffffu, p, 8);
        p += __shfl_xor_sync(0xffffffffu, p, 4);
        p += __shfl_xor_sync(0xffffffffu, p, 2);
        p += __shfl_xor_sync(0xffffffffu, p, 1);

        if (n == 0) {
            const float zv = xz[(size_t)m*NXZ + DINNER + d];
            y[(size_t)m*DINNER + d] = (p + Dd*xv) * (zv / (1.f + __expf(-zv)));
        }
    }
}

// ----------------------------------------------------------------------------
// Launch
// ----------------------------------------------------------------------------
extern "C" void kernel_launch(void* const* d_in, const int* in_sizes, int n_in,
                              void* d_out, int out_size)
{
    const float* x          = (const float*)d_in[0];
    const float* in_proj_w  = (const float*)d_in[1];
    const float* conv_w     = (const float*)d_in[2];
    const float* conv_b     = (const float*)d_in[3];
    const float* x_proj_w   = (const float*)d_in[4];
    const float* dt_proj_w  = (const float*)d_in[5];
    const float* dt_proj_b  = (const float*)d_in[6];
    const float* A_log      = (const float*)d_in[7];
    const float* D_param    = (const float*)d_in[8];
    const float* out_proj_w = (const float*)d_in[9];
    float* out = (float*)d_out;

    float *xz, *xc, *dbl, *dtb, *yb;
    cudaGetSymbolAddress((void**)&xz,  g_xz);
    cudaGetSymbolAddress((void**)&xc,  g_xc);
    cudaGetSymbolAddress((void**)&dbl, g_dbl);
    cudaGetSymbolAddress((void**)&dtb, g_dt);
    cudaGetSymbolAddress((void**)&yb,  g_y);

    // 1) xz = x @ in_proj_w^T : M=8192 N=4096 K=1024
    {
        dim3 grid(NXZ/128, MROWS/128);
        sgemm_nt<128,128,8,8,8,0><<<grid, 256>>>(x, in_proj_w, xz, nullptr,
                                                 MROWS, NXZ, DMODEL,
                                                 DMODEL, DMODEL, NXZ);
    }
    // 2) depthwise conv + silu
    {
        int total = MROWS * DINNER;
        conv_silu_kernel<<<total/256, 256>>>(xz, conv_w, conv_b, xc);
    }
    // 3) dbl = xc @ x_proj_w^T : M=8192 N=96 K=2048  (small-N config)
    {
        dim3 grid(1, MROWS/64);
        sgemm_nt<64,128,8,4,8,0><<<grid, 256>>>(xc, x_proj_w, dbl, nullptr,
                                                MROWS, NDBL, DINNER,
                                                DINNER, DINNER, NDBL);
    }
    // 4) dt = softplus(dbl[:, :64] @ dt_proj_w^T + b) : M=8192 N=2048 K=64
    {
        dim3 grid(DINNER/128, MROWS/128);
        sgemm_nt<128,128,8,8,8,1><<<grid, 256>>>(dbl, dt_proj_w, dtb, dt_proj_b,
                                                 MROWS, DINNER, DTRANK,
                                                 NDBL, DTRANK, DINNER);
    }
    // 5) selective scan + gating
    {
        dim3 grid(DINNER/16, BATCH);
        scan_kernel<<<grid, 256>>>(dtb, dbl, xc, xz, A_log, D_param, yb);
    }
    // 6) out = y @ out_proj_w^T : M=8192 N=1024 K=2048
    {
        dim3 grid(DMODEL/128, MROWS/128);
        sgemm_nt<128,128,8,8,8,0><<<grid, 256>>>(yb, out_proj_w, out, nullptr,
                                                 MROWS, DMODEL, DINNER,
                                                 DINNER, DINNER, DMODEL);
    }
}

// round 2
// speedup vs baseline: 1.0323x; 1.0323x over previous
#include <cuda_runtime.h>
#include <math.h>
#include <stdint.h>

// Problem constants
#define BATCH   4
#define SEQ     2048
#define DMODEL  1024
#define DINNER  2048
#define DSTATE  16
#define DTRANK  64
#define DCONV   4
#define MROWS   (BATCH*SEQ)          // 8192
#define NXZ     (2*DINNER)           // 4096
#define NDBL    (DTRANK + 2*DSTATE)  // 96

// ----------------------------------------------------------------------------
// Scratch (device globals; no runtime allocation allowed)
// ----------------------------------------------------------------------------
__device__ float g_xz [(size_t)MROWS * NXZ];     // in_proj output (x_ssm | z)
__device__ float g_xc [(size_t)MROWS * DINNER];  // conv+silu output
__device__ float g_dbl[(size_t)MROWS * NDBL];    // x_proj output (dt_x | B | C)
__device__ float g_dt [(size_t)MROWS * DINNER];  // softplus(dt)
__device__ float g_y  [(size_t)MROWS * DINNER];  // gated scan output

// ----------------------------------------------------------------------------
// Packed f32x2 helpers (Blackwell FFMA2 — ptxas never auto-emits this)
// ----------------------------------------------------------------------------
__device__ __forceinline__ unsigned long long pack2(float x) {
    unsigned long long r;
    asm("mov.b64 %0, {%1, %1};" : "=l"(r) : "f"(x));
    return r;
}
__device__ __forceinline__ void fma2(unsigned long long &d,
                                     unsigned long long a,
                                     unsigned long long b) {
    asm("fma.rn.f32x2 %0, %1, %2, %0;" : "+l"(d) : "l"(a), "l"(b));
}
__device__ __forceinline__ void unpack2(unsigned long long v, float &lo, float &hi) {
    asm("mov.b64 {%0, %1}, %2;" : "=f"(lo), "=f"(hi) : "l"(v));
}

// ----------------------------------------------------------------------------
// Generic NT SGEMM: C[M,N] = A[M,K] * B[N,K]^T  (+ optional softplus(bias) epi)
// Inner loop uses packed fma.rn.f32x2 (2 fp32 FMA / instruction).
// EPI: 0 = none, 1 = softplus(acc + bias[col])
// ----------------------------------------------------------------------------
template<int BM, int BN, int BK, int TM, int TN, int EPI>
__global__ void __launch_bounds__((BM/TM)*(BN/TN))
sgemm_nt(const float* __restrict__ A, const float* __restrict__ B,
         float* __restrict__ C, const float* __restrict__ bias,
         int M, int N, int K, int lda, int ldb, int ldc)
{
    constexpr int NT = (BM/TM)*(BN/TN);
    constexpr int TX = BN/TN;
    constexpr int KV = BK/4;
    constexpr int TN2 = TN/2;
    static_assert(NT == 256, "expect 256 threads");
    static_assert((TN & 1) == 0, "TN must be even");

    __shared__ float As[BK][BM];
    __shared__ float Bs[BK][BN];

    const int tid = threadIdx.x;
    const int tx  = tid % TX;
    const int ty  = tid / TX;
    const int rowBase = blockIdx.y * BM;
    const int colBase = blockIdx.x * BN;

    // Per-thread global-load coordinates (one float4 each, maybe predicated)
    const int  aRow = tid / KV;
    const int  aK   = (tid % KV) * 4;
    const bool aVal = (tid < BM*KV);
    const int  bRow = tid / KV;
    const int  bK   = (tid % KV) * 4;
    const bool bVal = (tid < BN*KV);

    const int nk = K / BK;

    unsigned long long acc2[TM][TN2];
#pragma unroll
    for (int i = 0; i < TM; ++i)
#pragma unroll
        for (int j = 0; j < TN2; ++j) acc2[i][j] = 0ull;

    float4 aReg = make_float4(0,0,0,0);
    float4 bReg = make_float4(0,0,0,0);

    // ---- load tile 0
    if (aVal) {
        int gr = rowBase + aRow;
        if (gr < M) aReg = *reinterpret_cast<const float4*>(&A[(size_t)gr*lda + aK]);
    }
    if (bVal) {
        int gr = colBase + bRow;
        if (gr < N) bReg = *reinterpret_cast<const float4*>(&B[(size_t)gr*ldb + bK]);
        else        bReg = make_float4(0,0,0,0);
    }
    if (aVal) {
        As[aK+0][aRow] = aReg.x; As[aK+1][aRow] = aReg.y;
        As[aK+2][aRow] = aReg.z; As[aK+3][aRow] = aReg.w;
    }
    if (bVal) {
        Bs[bK+0][bRow] = bReg.x; Bs[bK+1][bRow] = bReg.y;
        Bs[bK+2][bRow] = bReg.z; Bs[bK+3][bRow] = bReg.w;
    }
    __syncthreads();

    for (int kt = 0; kt < nk; ++kt) {
        // prefetch next tile into registers while computing current
        if (kt + 1 < nk) {
            const int ko = (kt+1)*BK;
            if (aVal) {
                int gr = rowBase + aRow;
                aReg = (gr < M) ? *reinterpret_cast<const float4*>(&A[(size_t)gr*lda + ko + aK])
                                : make_float4(0,0,0,0);
            }
            if (bVal) {
                int gr = colBase + bRow;
                bReg = (gr < N) ? *reinterpret_cast<const float4*>(&B[(size_t)gr*ldb + ko + bK])
                                : make_float4(0,0,0,0);
            }
        }

#pragma unroll
        for (int kk = 0; kk < BK; ++kk) {
            float ra[TM];
#pragma unroll
            for (int i = 0; i < TM; i += 4)
                *reinterpret_cast<float4*>(&ra[i]) =
                    *reinterpret_cast<const float4*>(&As[kk][ty*TM + i]);

            unsigned long long rb2[TN2];
            const unsigned long long* bsrow =
                reinterpret_cast<const unsigned long long*>(&Bs[kk][tx*TN]);
#pragma unroll
            for (int j = 0; j < TN2; ++j) rb2[j] = bsrow[j];

#pragma unroll
            for (int i = 0; i < TM; ++i) {
                const unsigned long long ra2 = pack2(ra[i]);
#pragma unroll
                for (int j = 0; j < TN2; ++j)
                    fma2(acc2[i][j], ra2, rb2[j]);
            }
        }
        __syncthreads();
        if (kt + 1 < nk) {
            if (aVal) {
                As[aK+0][aRow] = aReg.x; As[aK+1][aRow] = aReg.y;
                As[aK+2][aRow] = aReg.z; As[aK+3][aRow] = aReg.w;
            }
            if (bVal) {
                Bs[bK+0][bRow] = bReg.x; Bs[bK+1][bRow] = bReg.y;
                Bs[bK+2][bRow] = bReg.z; Bs[bK+3][bRow] = bReg.w;
            }
            __syncthreads();
        }
    }

    // ---- epilogue
#pragma unroll
    for (int i = 0; i < TM; ++i) {
        int r = rowBase + ty*TM + i;
        if (r >= M) continue;
#pragma unroll
        for (int j = 0; j < TN2; ++j) {
            float vlo, vhi;
            unpack2(acc2[i][j], vlo, vhi);
            int c = colBase + tx*TN + 2*j;
            if (EPI == 1) {
                float b0 = bias[c], b1 = bias[c+1];
                vlo += b0;
                vlo = fmaxf(vlo, 0.f) + log1pf(__expf(-fabsf(vlo)));
                vhi += b1;
                vhi = fmaxf(vhi, 0.f) + log1pf(__expf(-fabsf(vhi)));
            }
            if (c   < N) C[(size_t)r*ldc + c]     = vlo;
            if (c+1 < N) C[(size_t)r*ldc + c + 1] = vhi;
        }
    }
}

// ----------------------------------------------------------------------------
// Depthwise causal conv (width 4) + SiLU, reading x_ssm half of xz
// ----------------------------------------------------------------------------
__global__ void conv_silu_kernel(const float* __restrict__ xz,
                                 const float* __restrict__ w,
                                 const float* __restrict__ b,
                                 float* __restrict__ xc)
{
    int idx = blockIdx.x * blockDim.x + threadIdx.x;   // over MROWS*DINNER
    int d = idx & (DINNER - 1);
    int m = idx >> 11;                                  // DINNER = 2048 = 2^11
    int l = m & (SEQ - 1);

    float acc = b[d];
#pragma unroll
    for (int j = 0; j < DCONV; ++j) {
        int lj = l - (DCONV - 1) + j;
        if (lj >= 0)
            acc = fmaf(w[d*DCONV + j], xz[(size_t)(m - (DCONV-1) + j) * NXZ + d], acc);
    }
    xc[(size_t)idx] = acc / (1.f + __expf(-acc));       // silu
}

// ----------------------------------------------------------------------------
// Selective scan: one lane per (channel d, state n). 16 lanes per channel,
// 2 channels per warp, 8 warps per block -> 16 channels / block.
// Fuses  y = (scan + D*x) * silu(z).
// ----------------------------------------------------------------------------
__global__ void __launch_bounds__(256) scan_kernel(
    const float* __restrict__ dt,  const float* __restrict__ dbl,
    const float* __restrict__ xc,  const float* __restrict__ xz,
    const float* __restrict__ A_log, const float* __restrict__ Dp,
    float* __restrict__ y)
{
    const int lane = threadIdx.x & 31;
    const int warp = threadIdx.x >> 5;
    const int n    = lane & 15;
    const int d    = blockIdx.x * 16 + warp * 2 + (lane >> 4);
    const int b    = blockIdx.y;

    const float Ad = -__expf(A_log[d*DSTATE + n]);
    const float Dd = Dp[d];
    float h = 0.f;

    const int m0 = b * SEQ;
    for (int l = 0; l < SEQ; ++l) {
        const int m = m0 + l;
        const float dtv = dt [(size_t)m*DINNER + d];
        const float xv  = xc [(size_t)m*DINNER + d];
        const float Bv  = dbl[m*NDBL + DTRANK + n];
        const float Cv  = dbl[m*NDBL + DTRANK + DSTATE + n];

        const float dA = __expf(dtv * Ad);
        h = fmaf(dA, h, dtv * Bv * xv);

        float p = h * Cv;
        p += __shfl_xor_sync(0xffffffffu, p, 8);
        p += __shfl_xor_sync(0xffffffffu, p, 4);
        p += __shfl_xor_sync(0xffffffffu, p, 2);
        p += __shfl_xor_sync(0xffffffffu, p, 1);

        if (n == 0) {
            const float zv = xz[(size_t)m*NXZ + DINNER + d];
            y[(size_t)m*DINNER + d] = (p + Dd*xv) * (zv / (1.f + __expf(-zv)));
        }
    }
}

// ----------------------------------------------------------------------------
// Launch
// ----------------------------------------------------------------------------
extern "C" void kernel_launch(void* const* d_in, const int* in_sizes, int n_in,
                              void* d_out, int out_size)
{
    const float* x          = (const float*)d_in[0];
    const float* in_proj_w  = (const float*)d_in[1];
    const float* conv_w     = (const float*)d_in[2];
    const float* conv_b     = (const float*)d_in[3];
    const float* x_proj_w   = (const float*)d_in[4];
    const float* dt_proj_w  = (const float*)d_in[5];
    const float* dt_proj_b  = (const float*)d_in[6];
    const float* A_log      = (const float*)d_in[7];
    const float* D_param    = (const float*)d_in[8];
    const float* out_proj_w = (const float*)d_in[9];
    float* out = (float*)d_out;

    float *xz, *xc, *dbl, *dtb, *yb;
    cudaGetSymbolAddress((void**)&xz,  g_xz);
    cudaGetSymbolAddress((void**)&xc,  g_xc);
    cudaGetSymbolAddress((void**)&dbl, g_dbl);
    cudaGetSymbolAddress((void**)&dtb, g_dt);
    cudaGetSymbolAddress((void**)&yb,  g_y);

    // 1) xz = x @ in_proj_w^T : M=8192 N=4096 K=1024
    {
        dim3 grid(NXZ/128, MROWS/128);
        sgemm_nt<128,128,8,8,8,0><<<grid, 256>>>(x, in_proj_w, xz, nullptr,
                                                 MROWS, NXZ, DMODEL,
                                                 DMODEL, DMODEL, NXZ);
    }
    // 2) depthwise conv + silu
    {
        int total = MROWS * DINNER;
        conv_silu_kernel<<<total/256, 256>>>(xz, conv_w, conv_b, xc);
    }
    // 3) dbl = xc @ x_proj_w^T : M=8192 N=96 K=2048  (re-tiled 128x32)
    {
        dim3 grid(NDBL/32, MROWS/128);
        sgemm_nt<128,32,8,4,4,0><<<grid, 256>>>(xc, x_proj_w, dbl, nullptr,
                                                MROWS, NDBL, DINNER,
                                                DINNER, DINNER, NDBL);
    }
    // 4) dt = softplus(dbl[:, :64] @ dt_proj_w^T + b) : M=8192 N=2048 K=64
    {
        dim3 grid(DINNER/128, MROWS/128);
        sgemm_nt<128,128,8,8,8,1><<<grid, 256>>>(dbl, dt_proj_w, dtb, dt_proj_b,
                                                 MROWS, DINNER, DTRANK,
                                                 NDBL, DTRANK, DINNER);
    }
    // 5) selective scan + gating
    {
        dim3 grid(DINNER/16, BATCH);
        scan_kernel<<<grid, 256>>>(dtb, dbl, xc, xz, A_log, D_param, yb);
    }
    // 6) out = y @ out_proj_w^T : M=8192 N=1024 K=2048
    {
        dim3 grid(DMODEL/128, MROWS/128);
        sgemm_nt<128,128,8,8,8,0><<<grid, 256>>>(yb, out_proj_w, out, nullptr,
                                                 MROWS, DMODEL, DINNER,
                                                 DINNER, DINNER, DMODEL);
    }
}

// round 4
// speedup vs baseline: 1.6686x; 1.6164x over previous
#include <cuda_runtime.h>
#include <math.h>
#include <stdint.h>

// Problem constants
#define BATCH   4
#define SEQ     2048
#define DMODEL  1024
#define DINNER  2048
#define DSTATE  16
#define DTRANK  64
#define DCONV   4
#define MROWS   (BATCH*SEQ)          // 8192
#define NXZ     (2*DINNER)           // 4096
#define NDBL    (DTRANK + 2*DSTATE)  // 96

// ----------------------------------------------------------------------------
// Scratch (device globals; no runtime allocation allowed)
// ----------------------------------------------------------------------------
__device__ float g_xz [(size_t)MROWS * NXZ];     // in_proj output (x_ssm | z)
__device__ float g_xc [(size_t)MROWS * DINNER];  // conv+silu output
__device__ float g_dbl[(size_t)MROWS * NDBL];    // x_proj output (dt_x | B | C)
__device__ float g_dt [(size_t)MROWS * DINNER];  // softplus(dt)
__device__ float g_y  [(size_t)MROWS * DINNER];  // gated scan output

// ============================================================================
// mma.sync tf32 helpers (sm_80+ PTX — compiles under compute_103)
// ============================================================================
__device__ __forceinline__ uint32_t f2tf32(float x) {
    uint32_t r;
    asm("cvt.rna.tf32.f32 %0, %1;" : "=r"(r) : "f"(x));
    return r;
}
__device__ __forceinline__ void mma_tf32(float* c, const uint32_t* a, const uint32_t* b) {
    asm volatile(
        "mma.sync.aligned.m16n8k8.row.col.f32.tf32.tf32.f32 "
        "{%0,%1,%2,%3}, {%4,%5,%6,%7}, {%8,%9}, {%0,%1,%2,%3};"
        : "+f"(c[0]), "+f"(c[1]), "+f"(c[2]), "+f"(c[3])
        : "r"(a[0]), "r"(a[1]), "r"(a[2]), "r"(a[3]), "r"(b[0]), "r"(b[1]));
}
__device__ __forceinline__ uint32_t smem_u32(const void* p) {
    uint32_t a;
    asm("{ .reg .u64 t; cvta.to.shared.u64 t, %1; cvt.u32.u64 %0, t; }"
        : "=r"(a) : "l"(p));
    return a;
}
__device__ __forceinline__ void cp_async16(uint32_t dst, const void* src) {
    asm volatile("cp.async.ca.shared.global [%0], [%1], 16;"
                 :: "r"(dst), "l"(src) : "memory");
}
#define CP_COMMIT() asm volatile("cp.async.commit_group;" ::: "memory")
#define CP_WAIT(n)  asm volatile("cp.async.wait_group %0;" :: "n"(n) : "memory")

// ============================================================================
// tf32 MMA NT GEMM: C[M,N] = A[M,K] * B[N,K]^T, fp32 accumulate.
// CTA tile 128x128x32, 256 thr (8 warps 2x4), warp tile 64x32,
// cp.async double-buffered smem (stride 36 floats: frag LDS conflict-free).
// ============================================================================
#define MMA_STRIDE   36
#define MMA_STAGE_F  (128 * MMA_STRIDE)          // floats per operand stage
#define MMA_STAGE_B  (MMA_STAGE_F * 4)           // 18432 bytes
#define MMA_SMEM_B   (4 * MMA_STAGE_B)           // 73728 bytes

__global__ void __launch_bounds__(256, 2)
mma_gemm_tf32(const float* __restrict__ A, const float* __restrict__ B,
              float* __restrict__ C, int M, int N, int K,
              int lda, int ldb, int ldc)
{
    extern __shared__ float sm[];
    const uint32_t smB = smem_u32(sm);

    const int tid    = threadIdx.x;
    const int lane   = tid & 31;
    const int wid    = tid >> 5;
    const int warp_m = wid >> 2;      // 0..1  (64 rows each)
    const int warp_n = wid & 3;       // 0..3  (32 cols each)
    const int lr     = lane >> 2;     // 0..7
    const int lc     = lane & 3;      // 0..3

    const int rowBase = blockIdx.y * 128;
    const int colBase = blockIdx.x * 128;

    float acc[4][4][4];
#pragma unroll
    for (int mt = 0; mt < 4; ++mt)
#pragma unroll
        for (int nt = 0; nt < 4; ++nt)
#pragma unroll
            for (int i = 0; i < 4; ++i) acc[mt][nt][i] = 0.f;

    const int T = K >> 5;             // K/32 tiles

    // ---- async tile loader: 128 rows x 32 floats per operand ----
    auto load_stage = [&](int s, int kt) {
        const int kOff = kt << 5;
        const uint32_t aB = smB + s * MMA_STAGE_B;
        const uint32_t bB = smB + 2 * MMA_STAGE_B + s * MMA_STAGE_B;
#pragma unroll
        for (int i = 0; i < 4; ++i) {
            const int chunk = tid + (i << 8);
            const int row = chunk >> 3;
            const int c4  = chunk & 7;
            const uint32_t so = row * (MMA_STRIDE * 4) + c4 * 16;
            cp_async16(aB + so, &A[(size_t)(rowBase + row) * lda + kOff + c4 * 4]);
            cp_async16(bB + so, &B[(size_t)(colBase + row) * ldb + kOff + c4 * 4]);
        }
        CP_COMMIT();
    };

    load_stage(0, 0);

    for (int kt = 0; kt < T; ++kt) {
        const int s = kt & 1;
        if (kt + 1 < T) {
            load_stage(s ^ 1, kt + 1);
            CP_WAIT(1);
        } else {
            CP_WAIT(0);
        }
        __syncthreads();

        const float* As_ = sm + s * MMA_STAGE_F;
        const float* Bs_ = sm + 2 * MMA_STAGE_F + s * MMA_STAGE_F;

#pragma unroll
        for (int kk = 0; kk < 4; ++kk) {
            const int k0 = (kk << 3) + lc;
            uint32_t af[4][4];
#pragma unroll
            for (int mt = 0; mt < 4; ++mt) {
                const float* p = As_ + (warp_m * 64 + mt * 16 + lr) * MMA_STRIDE + k0;
                af[mt][0] = f2tf32(p[0]);
                af[mt][1] = f2tf32(p[8 * MMA_STRIDE]);
                af[mt][2] = f2tf32(p[4]);
                af[mt][3] = f2tf32(p[8 * MMA_STRIDE + 4]);
            }
            uint32_t bf[4][2];
#pragma unroll
            for (int nt = 0; nt < 4; ++nt) {
                const float* p = Bs_ + (warp_n * 32 + nt * 8 + lr) * MMA_STRIDE + k0;
                bf[nt][0] = f2tf32(p[0]);
                bf[nt][1] = f2tf32(p[4]);
            }
#pragma unroll
            for (int mt = 0; mt < 4; ++mt)
#pragma unroll
                for (int nt = 0; nt < 4; ++nt)
                    mma_tf32(acc[mt][nt], af[mt], bf[nt]);
        }
        __syncthreads();
    }

    // ---- epilogue: c0,c1 at (row, col..col+1), c2,c3 at (row+8, ...) ----
#pragma unroll
    for (int mt = 0; mt < 4; ++mt) {
        const int row = rowBase + warp_m * 64 + mt * 16 + lr;
#pragma unroll
        for (int nt = 0; nt < 4; ++nt) {
            const int col = colBase + warp_n * 32 + nt * 8 + 2 * lc;
            float2 v0 = make_float2(acc[mt][nt][0], acc[mt][nt][1]);
            float2 v1 = make_float2(acc[mt][nt][2], acc[mt][nt][3]);
            *reinterpret_cast<float2*>(&C[(size_t)row * ldc + col])       = v0;
            *reinterpret_cast<float2*>(&C[(size_t)(row + 8) * ldc + col]) = v1;
        }
    }
}

// ----------------------------------------------------------------------------
// Packed f32x2 helpers (Blackwell FFMA2)
// ----------------------------------------------------------------------------
__device__ __forceinline__ unsigned long long pack2(float x) {
    unsigned long long r;
    asm("mov.b64 %0, {%1, %1};" : "=l"(r) : "f"(x));
    return r;
}
__device__ __forceinline__ void fma2(unsigned long long &d,
                                     unsigned long long a,
                                     unsigned long long b) {
    asm("fma.rn.f32x2 %0, %1, %2, %0;" : "+l"(d) : "l"(a), "l"(b));
}
__device__ __forceinline__ void unpack2(unsigned long long v, float &lo, float &hi) {
    asm("mov.b64 {%0, %1}, %2;" : "=f"(lo), "=f"(hi) : "l"(v));
}

// ----------------------------------------------------------------------------
// FFMA2 NT SGEMM (small GEMMs): C = A*B^T (+softplus(bias) epi)
// ----------------------------------------------------------------------------
template<int BM, int BN, int BK, int TM, int TN, int EPI>
__global__ void __launch_bounds__((BM/TM)*(BN/TN))
sgemm_nt(const float* __restrict__ A, const float* __restrict__ B,
         float* __restrict__ C, const float* __restrict__ bias,
         int M, int N, int K, int lda, int ldb, int ldc)
{
    constexpr int NT = (BM/TM)*(BN/TN);
    constexpr int TX = BN/TN;
    constexpr int KV = BK/4;
    constexpr int TN2 = TN/2;
    static_assert(NT == 256, "expect 256 threads");

    __shared__ float As[BK][BM];
    __shared__ float Bs[BK][BN];

    const int tid = threadIdx.x;
    const int tx  = tid % TX;
    const int ty  = tid / TX;
    const int rowBase = blockIdx.y * BM;
    const int colBase = blockIdx.x * BN;

    const int  aRow = tid / KV;
    const int  aK   = (tid % KV) * 4;
    const bool aVal = (tid < BM*KV);
    const int  bRow = tid / KV;
    const int  bK   = (tid % KV) * 4;
    const bool bVal = (tid < BN*KV);

    const int nk = K / BK;

    unsigned long long acc2[TM][TN2];
#pragma unroll
    for (int i = 0; i < TM; ++i)
#pragma unroll
        for (int j = 0; j < TN2; ++j) acc2[i][j] = 0ull;

    float4 aReg = make_float4(0,0,0,0);
    float4 bReg = make_float4(0,0,0,0);

    if (aVal) {
        int gr = rowBase + aRow;
        if (gr < M) aReg = *reinterpret_cast<const float4*>(&A[(size_t)gr*lda + aK]);
    }
    if (bVal) {
        int gr = colBase + bRow;
        bReg = (gr < N) ? *reinterpret_cast<const float4*>(&B[(size_t)gr*ldb + bK])
                        : make_float4(0,0,0,0);
    }
    if (aVal) {
        As[aK+0][aRow] = aReg.x; As[aK+1][aRow] = aReg.y;
        As[aK+2][aRow] = aReg.z; As[aK+3][aRow] = aReg.w;
    }
    if (bVal) {
        Bs[bK+0][bRow] = bReg.x; Bs[bK+1][bRow] = bReg.y;
        Bs[bK+2][bRow] = bReg.z; Bs[bK+3][bRow] = bReg.w;
    }
    __syncthreads();

    for (int kt = 0; kt < nk; ++kt) {
        if (kt + 1 < nk) {
            const int ko = (kt+1)*BK;
            if (aVal) {
                int gr = rowBase + aRow;
                aReg = (gr < M) ? *reinterpret_cast<const float4*>(&A[(size_t)gr*lda + ko + aK])
                                : make_float4(0,0,0,0);
            }
            if (bVal) {
                int gr = colBase + bRow;
                bReg = (gr < N) ? *reinterpret_cast<const float4*>(&B[(size_t)gr*ldb + ko + bK])
                                : make_float4(0,0,0,0);
            }
        }

#pragma unroll
        for (int kk = 0; kk < BK; ++kk) {
            float ra[TM];
#pragma unroll
            for (int i = 0; i < TM; i += 4)
                *reinterpret_cast<float4*>(&ra[i]) =
                    *reinterpret_cast<const float4*>(&As[kk][ty*TM + i]);

            unsigned long long rb2[TN2];
            const unsigned long long* bsrow =
                reinterpret_cast<const unsigned long long*>(&Bs[kk][tx*TN]);
#pragma unroll
            for (int j = 0; j < TN2; ++j) rb2[j] = bsrow[j];

#pragma unroll
            for (int i = 0; i < TM; ++i) {
                const unsigned long long ra2 = pack2(ra[i]);
#pragma unroll
                for (int j = 0; j < TN2; ++j)
                    fma2(acc2[i][j], ra2, rb2[j]);
            }
        }
        __syncthreads();
        if (kt + 1 < nk) {
            if (aVal) {
                As[aK+0][aRow] = aReg.x; As[aK+1][aRow] = aReg.y;
                As[aK+2][aRow] = aReg.z; As[aK+3][aRow] = aReg.w;
            }
            if (bVal) {
                Bs[bK+0][bRow] = bReg.x; Bs[bK+1][bRow] = bReg.y;
                Bs[bK+2][bRow] = bReg.z; Bs[bK+3][bRow] = bReg.w;
            }
            __syncthreads();
        }
    }

#pragma unroll
    for (int i = 0; i < TM; ++i) {
        int r = rowBase + ty*TM + i;
        if (r >= M) continue;
#pragma unroll
        for (int j = 0; j < TN2; ++j) {
            float vlo, vhi;
            unpack2(acc2[i][j], vlo, vhi);
            int c = colBase + tx*TN + 2*j;
            if (EPI == 1) {
                float b0 = bias[c], b1 = bias[c+1];
                vlo += b0;
                vlo = fmaxf(vlo, 0.f) + log1pf(__expf(-fabsf(vlo)));
                vhi += b1;
                vhi = fmaxf(vhi, 0.f) + log1pf(__expf(-fabsf(vhi)));
            }
            if (c   < N) C[(size_t)r*ldc + c]     = vlo;
            if (c+1 < N) C[(size_t)r*ldc + c + 1] = vhi;
        }
    }
}

// ----------------------------------------------------------------------------
// Depthwise causal conv (width 4) + SiLU
// ----------------------------------------------------------------------------
__global__ void conv_silu_kernel(const float* __restrict__ xz,
                                 const float* __restrict__ w,
                                 const float* __restrict__ b,
                                 float* __restrict__ xc)
{
    int idx = blockIdx.x * blockDim.x + threadIdx.x;
    int d = idx & (DINNER - 1);
    int m = idx >> 11;
    int l = m & (SEQ - 1);

    float acc = b[d];
#pragma unroll
    for (int j = 0; j < DCONV; ++j) {
        int lj = l - (DCONV - 1) + j;
        if (lj >= 0)
            acc = fmaf(w[d*DCONV + j], xz[(size_t)(m - (DCONV-1) + j) * NXZ + d], acc);
    }
    xc[(size_t)idx] = acc / (1.f + __expf(-acc));
}

// ----------------------------------------------------------------------------
// Selective scan: one lane per (channel d, state n).
// ----------------------------------------------------------------------------
__global__ void __launch_bounds__(256) scan_kernel(
    const float* __restrict__ dt,  const float* __restrict__ dbl,
    const float* __restrict__ xc,  const float* __restrict__ xz,
    const float* __restrict__ A_log, const float* __restrict__ Dp,
    float* __restrict__ y)
{
    const int lane = threadIdx.x & 31;
    const int warp = threadIdx.x >> 5;
    const int n    = lane & 15;
    const int d    = blockIdx.x * 16 + warp * 2 + (lane >> 4);
    const int b    = blockIdx.y;

    const float Ad = -__expf(A_log[d*DSTATE + n]);
    const float Dd = Dp[d];
    float h = 0.f;

    const int m0 = b * SEQ;
    for (int l = 0; l < SEQ; ++l) {
        const int m = m0 + l;
        const float dtv = dt [(size_t)m*DINNER + d];
        const float xv  = xc [(size_t)m*DINNER + d];
        const float Bv  = dbl[m*NDBL + DTRANK + n];
        const float Cv  = dbl[m*NDBL + DTRANK + DSTATE + n];

        const float dA = __expf(dtv * Ad);
        h = fmaf(dA, h, dtv * Bv * xv);

        float p = h * Cv;
        p += __shfl_xor_sync(0xffffffffu, p, 8);
        p += __shfl_xor_sync(0xffffffffu, p, 4);
        p += __shfl_xor_sync(0xffffffffu, p, 2);
        p += __shfl_xor_sync(0xffffffffu, p, 1);

        if (n == 0) {
            const float zv = xz[(size_t)m*NXZ + DINNER + d];
            y[(size_t)m*DINNER + d] = (p + Dd*xv) * (zv / (1.f + __expf(-zv)));
        }
    }
}

// ----------------------------------------------------------------------------
// Launch
// ----------------------------------------------------------------------------
extern "C" void kernel_launch(void* const* d_in, const int* in_sizes, int n_in,
                              void* d_out, int out_size)
{
    const float* x          = (const float*)d_in[0];
    const float* in_proj_w  = (const float*)d_in[1];
    const float* conv_w     = (const float*)d_in[2];
    const float* conv_b     = (const float*)d_in[3];
    const float* x_proj_w   = (const float*)d_in[4];
    const float* dt_proj_w  = (const float*)d_in[5];
    const float* dt_proj_b  = (const float*)d_in[6];
    const float* A_log      = (const float*)d_in[7];
    const float* D_param    = (const float*)d_in[8];
    const float* out_proj_w = (const float*)d_in[9];
    float* out = (float*)d_out;

    float *xz, *xc, *dbl, *dtb, *yb;
    cudaGetSymbolAddress((void**)&xz,  g_xz);
    cudaGetSymbolAddress((void**)&xc,  g_xc);
    cudaGetSymbolAddress((void**)&dbl, g_dbl);
    cudaGetSymbolAddress((void**)&dtb, g_dt);
    cudaGetSymbolAddress((void**)&yb,  g_y);

    cudaFuncSetAttribute(mma_gemm_tf32,
                         cudaFuncAttributeMaxDynamicSharedMemorySize,
                         MMA_SMEM_B);

    // 1) xz = x @ in_proj_w^T : M=8192 N=4096 K=1024  (tf32 mma)
    {
        dim3 grid(NXZ/128, MROWS/128);
        mma_gemm_tf32<<<grid, 256, MMA_SMEM_B>>>(x, in_proj_w, xz,
                                                 MROWS, NXZ, DMODEL,
                                                 DMODEL, DMODEL, NXZ);
    }
    // 2) depthwise conv + silu
    {
        int total = MROWS * DINNER;
        conv_silu_kernel<<<total/256, 256>>>(xz, conv_w, conv_b, xc);
    }
    // 3) dbl = xc @ x_proj_w^T : M=8192 N=96 K=2048  (FFMA2)
    {
        dim3 grid(NDBL/32, MROWS/128);
        sgemm_nt<128,32,8,4,4,0><<<grid, 256>>>(xc, x_proj_w, dbl, nullptr,
                                                MROWS, NDBL, DINNER,
                                                DINNER, DINNER, NDBL);
    }
    // 4) dt = softplus(dbl[:, :64] @ dt_proj_w^T + b) : M=8192 N=2048 K=64 (FFMA2)
    {
        dim3 grid(DINNER/128, MROWS/128);
        sgemm_nt<128,128,8,8,8,1><<<grid, 256>>>(dbl, dt_proj_w, dtb, dt_proj_b,
                                                 MROWS, DINNER, DTRANK,
                                                 NDBL, DTRANK, DINNER);
    }
    // 5) selective scan + gating
    {
        dim3 grid(DINNER/16, BATCH);
        scan_kernel<<<grid, 256>>>(dtb, dbl, xc, xz, A_log, D_param, yb);
    }
    // 6) out = y @ out_proj_w^T : M=8192 N=1024 K=2048  (tf32 mma)
    {
        dim3 grid(DMODEL/128, MROWS/128);
        mma_gemm_tf32<<<grid, 256, MMA_SMEM_B>>>(yb, out_proj_w, out,
                                                 MROWS, DMODEL, DINNER,
                                                 DINNER, DINNER, DMODEL);
    }
}

// round 5
// speedup vs baseline: 1.7865x; 1.0707x over previous
#include <cuda_runtime.h>
#include <math.h>
#include <stdint.h>

// Problem constants
#define BATCH   4
#define SEQ     2048
#define DMODEL  1024
#define DINNER  2048
#define DSTATE  16
#define DTRANK  64
#define DCONV   4
#define MROWS   (BATCH*SEQ)          // 8192
#define NXZ     (2*DINNER)           // 4096
#define NDBL    (DTRANK + 2*DSTATE)  // 96

// ----------------------------------------------------------------------------
// Scratch (device globals; no runtime allocation allowed)
// ----------------------------------------------------------------------------
__device__ float g_xz [(size_t)MROWS * NXZ];       // in_proj output (x_ssm | z)
__device__ float g_xc [(size_t)MROWS * DINNER];    // conv+silu output
__device__ float g_dbl[(size_t)MROWS * NDBL];      // x_proj output (dt_x | B | C)
__device__ float g_dt [(size_t)MROWS * DINNER];    // softplus(dt)
__device__ float g_y  [(size_t)MROWS * DINNER];    // gated scan output (tf32-rounded)
__device__ float g_xr [(size_t)MROWS * DMODEL];    // tf32-rounded x
__device__ float g_wa [(size_t)NXZ   * DMODEL];    // tf32-rounded in_proj_w
__device__ float g_wb [(size_t)DMODEL* DINNER];    // tf32-rounded out_proj_w

// ============================================================================
// mma.sync tf32 helpers (sm_80+ PTX — compiles under compute_103)
// ============================================================================
__device__ __forceinline__ uint32_t f2tf32(float x) {
    uint32_t r;
    asm("cvt.rna.tf32.f32 %0, %1;" : "=r"(r) : "f"(x));
    return r;
}
__device__ __forceinline__ void mma_tf32(float* c, const uint32_t* a, const uint32_t* b) {
    asm volatile(
        "mma.sync.aligned.m16n8k8.row.col.f32.tf32.tf32.f32 "
        "{%0,%1,%2,%3}, {%4,%5,%6,%7}, {%8,%9}, {%0,%1,%2,%3};"
        : "+f"(c[0]), "+f"(c[1]), "+f"(c[2]), "+f"(c[3])
        : "r"(a[0]), "r"(a[1]), "r"(a[2]), "r"(a[3]), "r"(b[0]), "r"(b[1]));
}
__device__ __forceinline__ uint32_t smem_u32(const void* p) {
    uint32_t a;
    asm("{ .reg .u64 t; cvta.to.shared.u64 t, %1; cvt.u32.u64 %0, t; }"
        : "=r"(a) : "l"(p));
    return a;
}
__device__ __forceinline__ void cp_async16(uint32_t dst, const void* src) {
    asm volatile("cp.async.ca.shared.global [%0], [%1], 16;"
                 :: "r"(dst), "l"(src) : "memory");
}
// zero-fill variant: src_size=0 -> 16 bytes of zeros in smem
__device__ __forceinline__ void cp_async16z(uint32_t dst, const void* src, bool valid) {
    uint32_t sz = valid ? 16u : 0u;
    asm volatile("cp.async.ca.shared.global [%0], [%1], 16, %2;"
                 :: "r"(dst), "l"(src), "r"(sz) : "memory");
}
#define CP_COMMIT() asm volatile("cp.async.commit_group;" ::: "memory")
#define CP_WAIT(n)  asm volatile("cp.async.wait_group %0;" :: "n"(n) : "memory")

// ============================================================================
// tf32 MMA NT GEMM: C[M,N] = A[M,K] * B[N,K]^T, fp32 accumulate.
// CTA tile 128x128x32, 256 thr (8 warps 2x4), warp tile 64x32,
// cp.async double-buffered smem (stride 36 floats: frag LDS conflict-free).
// EPI:    0 = plain store, 1 = softplus(acc + bias[col])
// NGUARD: predicate B-tile loads and C stores against N (for N=96)
// CVTA/CVTB: round fragments to tf32 in-loop (when operand can't be pre-rounded)
// ============================================================================
#define MMA_STRIDE   36
#define MMA_STAGE_F  (128 * MMA_STRIDE)          // floats per operand stage
#define MMA_STAGE_B  (MMA_STAGE_F * 4)           // 18432 bytes
#define MMA_SMEM_B   (4 * MMA_STAGE_B)           // 73728 bytes

template<int EPI, bool NGUARD, bool CVTA, bool CVTB>
__global__ void __launch_bounds__(256, 2)
mma_gemm(const float* __restrict__ A, const float* __restrict__ B,
         float* __restrict__ C, const float* __restrict__ bias,
         int M, int N, int K, int lda, int ldb, int ldc)
{
    extern __shared__ float sm[];
    const uint32_t smB = smem_u32(sm);

    const int tid    = threadIdx.x;
    const int lane   = tid & 31;
    const int wid    = tid >> 5;
    const int warp_m = wid >> 2;      // 0..1  (64 rows each)
    const int warp_n = wid & 3;       // 0..3  (32 cols each)
    const int lr     = lane >> 2;     // 0..7
    const int lc     = lane & 3;      // 0..3

    const int rowBase = blockIdx.y * 128;
    const int colBase = blockIdx.x * 128;

    float acc[4][4][4];
#pragma unroll
    for (int mt = 0; mt < 4; ++mt)
#pragma unroll
        for (int nt = 0; nt < 4; ++nt)
#pragma unroll
            for (int i = 0; i < 4; ++i) acc[mt][nt][i] = 0.f;

    const int T = K >> 5;             // K/32 tiles

    // ---- async tile loader: 128 rows x 32 floats per operand ----
    auto load_stage = [&](int s, int kt) {
        const int kOff = kt << 5;
        const uint32_t aB = smB + s * MMA_STAGE_B;
        const uint32_t bB = smB + 2 * MMA_STAGE_B + s * MMA_STAGE_B;
#pragma unroll
        for (int i = 0; i < 4; ++i) {
            const int chunk = tid + (i << 8);
            const int row = chunk >> 3;
            const int c4  = chunk & 7;
            const uint32_t so = row * (MMA_STRIDE * 4) + c4 * 16;
            cp_async16(aB + so, &A[(size_t)(rowBase + row) * lda + kOff + c4 * 4]);
            if (NGUARD) {
                const bool ok = (colBase + row) < N;
                const int  br = ok ? (colBase + row) : 0;
                cp_async16z(bB + so, &B[(size_t)br * ldb + kOff + c4 * 4], ok);
            } else {
                cp_async16(bB + so, &B[(size_t)(colBase + row) * ldb + kOff + c4 * 4]);
            }
        }
        CP_COMMIT();
    };

    // fragment loader (raw bits, optional in-loop tf32 rounding)
    auto fragA = [&](const float* p) -> uint32_t {
        return CVTA ? f2tf32(*p) : __float_as_uint(*p);
    };
    auto fragB = [&](const float* p) -> uint32_t {
        return CVTB ? f2tf32(*p) : __float_as_uint(*p);
    };

    load_stage(0, 0);

    for (int kt = 0; kt < T; ++kt) {
        const int s = kt & 1;
        if (kt + 1 < T) {
            load_stage(s ^ 1, kt + 1);
            CP_WAIT(1);
        } else {
            CP_WAIT(0);
        }
        __syncthreads();

        const float* As_ = sm + s * MMA_STAGE_F;
        const float* Bs_ = sm + 2 * MMA_STAGE_F + s * MMA_STAGE_F;

#pragma unroll
        for (int kk = 0; kk < 4; ++kk) {
            const int k0 = (kk << 3) + lc;
            uint32_t af[4][4];
#pragma unroll
            for (int mt = 0; mt < 4; ++mt) {
                const float* p = As_ + (warp_m * 64 + mt * 16 + lr) * MMA_STRIDE + k0;
                af[mt][0] = fragA(p);
                af[mt][1] = fragA(p + 8 * MMA_STRIDE);
                af[mt][2] = fragA(p + 4);
                af[mt][3] = fragA(p + 8 * MMA_STRIDE + 4);
            }
            uint32_t bf[4][2];
#pragma unroll
            for (int nt = 0; nt < 4; ++nt) {
                const float* p = Bs_ + (warp_n * 32 + nt * 8 + lr) * MMA_STRIDE + k0;
                bf[nt][0] = fragB(p);
                bf[nt][1] = fragB(p + 4);
            }
#pragma unroll
            for (int mt = 0; mt < 4; ++mt)
#pragma unroll
                for (int nt = 0; nt < 4; ++nt)
                    mma_tf32(acc[mt][nt], af[mt], bf[nt]);
        }
        __syncthreads();
    }

    // ---- epilogue ----
#pragma unroll
    for (int mt = 0; mt < 4; ++mt) {
        const int row = rowBase + warp_m * 64 + mt * 16 + lr;
#pragma unroll
        for (int nt = 0; nt < 4; ++nt) {
            const int col = colBase + warp_n * 32 + nt * 8 + 2 * lc;
            if (NGUARD && col >= N) continue;
            float v[4] = {acc[mt][nt][0], acc[mt][nt][1],
                          acc[mt][nt][2], acc[mt][nt][3]};
            if (EPI == 1) {
                const float b0 = bias[col], b1 = bias[col + 1];
                v[0] += b0; v[1] += b1; v[2] += b0; v[3] += b1;
#pragma unroll
                for (int i = 0; i < 4; ++i)
                    v[i] = fmaxf(v[i], 0.f) + log1pf(__expf(-fabsf(v[i])));
            }
            *reinterpret_cast<float2*>(&C[(size_t)row * ldc + col]) =
                make_float2(v[0], v[1]);
            *reinterpret_cast<float2*>(&C[(size_t)(row + 8) * ldc + col]) =
                make_float2(v[2], v[3]);
        }
    }
}

// ----------------------------------------------------------------------------
// Round fp32 array to tf32 (rna) — vectorized elementwise pass
// ----------------------------------------------------------------------------
__global__ void round_tf32_kernel(const float4* __restrict__ in,
                                  float4* __restrict__ out, int n4)
{
    int i = blockIdx.x * blockDim.x + threadIdx.x;
    if (i < n4) {
        float4 v = in[i];
        v.x = __uint_as_float(f2tf32(v.x));
        v.y = __uint_as_float(f2tf32(v.y));
        v.z = __uint_as_float(f2tf32(v.z));
        v.w = __uint_as_float(f2tf32(v.w));
        out[i] = v;
    }
}

// ----------------------------------------------------------------------------
// Depthwise causal conv (width 4) + SiLU
// ----------------------------------------------------------------------------
__global__ void conv_silu_kernel(const float* __restrict__ xz,
                                 const float* __restrict__ w,
                                 const float* __restrict__ b,
                                 float* __restrict__ xc)
{
    int idx = blockIdx.x * blockDim.x + threadIdx.x;
    int d = idx & (DINNER - 1);
    int m = idx >> 11;
    int l = m & (SEQ - 1);

    float acc = b[d];
#pragma unroll
    for (int j = 0; j < DCONV; ++j) {
        int lj = l - (DCONV - 1) + j;
        if (lj >= 0)
            acc = fmaf(w[d*DCONV + j], xz[(size_t)(m - (DCONV-1) + j) * NXZ + d], acc);
    }
    xc[(size_t)idx] = acc / (1.f + __expf(-acc));
}

// ----------------------------------------------------------------------------
// Selective scan: one lane per (channel d, state n). Output rounded to tf32
// (it is consumed only by the tf32 out_proj GEMM).
// ----------------------------------------------------------------------------
__global__ void __launch_bounds__(256) scan_kernel(
    const float* __restrict__ dt,  const float* __restrict__ dbl,
    const float* __restrict__ xc,  const float* __restrict__ xz,
    const float* __restrict__ A_log, const float* __restrict__ Dp,
    float* __restrict__ y)
{
    const int lane = threadIdx.x & 31;
    const int warp = threadIdx.x >> 5;
    const int n    = lane & 15;
    const int d    = blockIdx.x * 16 + warp * 2 + (lane >> 4);
    const int b    = blockIdx.y;

    const float Ad = -__expf(A_log[d*DSTATE + n]);
    const float Dd = Dp[d];
    float h = 0.f;

    const int m0 = b * SEQ;
    for (int l = 0; l < SEQ; ++l) {
        const int m = m0 + l;
        const float dtv = dt [(size_t)m*DINNER + d];
        const float xv  = xc [(size_t)m*DINNER + d];
        const float Bv  = dbl[m*NDBL + DTRANK + n];
        const float Cv  = dbl[m*NDBL + DTRANK + DSTATE + n];

        const float dA = __expf(dtv * Ad);
        h = fmaf(dA, h, dtv * Bv * xv);

        float p = h * Cv;
        p += __shfl_xor_sync(0xffffffffu, p, 8);
        p += __shfl_xor_sync(0xffffffffu, p, 4);
        p += __shfl_xor_sync(0xffffffffu, p, 2);
        p += __shfl_xor_sync(0xffffffffu, p, 1);

        if (n == 0) {
            const float zv = xz[(size_t)m*NXZ + DINNER + d];
            const float yv = (p + Dd*xv) * (zv / (1.f + __expf(-zv)));
            y[(size_t)m*DINNER + d] = __uint_as_float(f2tf32(yv));
        }
    }
}

// ----------------------------------------------------------------------------
// Launch
// ----------------------------------------------------------------------------
extern "C" void kernel_launch(void* const* d_in, const int* in_sizes, int n_in,
                              void* d_out, int out_size)
{
    const float* x          = (const float*)d_in[0];
    const float* in_proj_w  = (const float*)d_in[1];
    const float* conv_w     = (const float*)d_in[2];
    const float* conv_b     = (const float*)d_in[3];
    const float* x_proj_w   = (const float*)d_in[4];
    const float* dt_proj_w  = (const float*)d_in[5];
    const float* dt_proj_b  = (const float*)d_in[6];
    const float* A_log      = (const float*)d_in[7];
    const float* D_param    = (const float*)d_in[8];
    const float* out_proj_w = (const float*)d_in[9];
    float* out = (float*)d_out;

    float *xz, *xc, *dbl, *dtb, *yb, *xr, *wa, *wb;
    cudaGetSymbolAddress((void**)&xz,  g_xz);
    cudaGetSymbolAddress((void**)&xc,  g_xc);
    cudaGetSymbolAddress((void**)&dbl, g_dbl);
    cudaGetSymbolAddress((void**)&dtb, g_dt);
    cudaGetSymbolAddress((void**)&yb,  g_y);
    cudaGetSymbolAddress((void**)&xr,  g_xr);
    cudaGetSymbolAddress((void**)&wa,  g_wa);
    cudaGetSymbolAddress((void**)&wb,  g_wb);

    cudaFuncSetAttribute((const void*)mma_gemm<0,false,false,false>,
                         cudaFuncAttributeMaxDynamicSharedMemorySize, MMA_SMEM_B);
    cudaFuncSetAttribute((const void*)mma_gemm<0,true,true,true>,
                         cudaFuncAttributeMaxDynamicSharedMemorySize, MMA_SMEM_B);
    cudaFuncSetAttribute((const void*)mma_gemm<1,false,true,true>,
                         cudaFuncAttributeMaxDynamicSharedMemorySize, MMA_SMEM_B);

    // 0) pre-round big GEMM operands to tf32 (removes CVT from mainloops)
    {
        int n4;
        n4 = MROWS * DMODEL / 4;
        round_tf32_kernel<<<(n4 + 255)/256, 256>>>((const float4*)x,
                                                   (float4*)xr, n4);
        n4 = NXZ * DMODEL / 4;
        round_tf32_kernel<<<(n4 + 255)/256, 256>>>((const float4*)in_proj_w,
                                                   (float4*)wa, n4);
        n4 = DMODEL * DINNER / 4;
        round_tf32_kernel<<<(n4 + 255)/256, 256>>>((const float4*)out_proj_w,
                                                   (float4*)wb, n4);
    }

    // 1) xz = x @ in_proj_w^T : M=8192 N=4096 K=1024  (tf32 mma, pre-rounded)
    {
        dim3 grid(NXZ/128, MROWS/128);
        mma_gemm<0,false,false,false><<<grid, 256, MMA_SMEM_B>>>(
            xr, wa, xz, nullptr, MROWS, NXZ, DMODEL, DMODEL, DMODEL, NXZ);
    }
    // 2) depthwise conv + silu
    {
        int total = MROWS * DINNER;
        conv_silu_kernel<<<total/256, 256>>>(xz, conv_w, conv_b, xc);
    }
    // 3) dbl = xc @ x_proj_w^T : M=8192 N=96 K=2048  (tf32 mma, in-loop cvt)
    {
        dim3 grid(1, MROWS/128);
        mma_gemm<0,true,true,true><<<grid, 256, MMA_SMEM_B>>>(
            xc, x_proj_w, dbl, nullptr, MROWS, NDBL, DINNER,
            DINNER, DINNER, NDBL);
    }
    // 4) dt = softplus(dbl[:, :64] @ dt_proj_w^T + b) : M=8192 N=2048 K=64
    {
        dim3 grid(DINNER/128, MROWS/128);
        mma_gemm<1,false,true,true><<<grid, 256, MMA_SMEM_B>>>(
            dbl, dt_proj_w, dtb, dt_proj_b, MROWS, DINNER, DTRANK,
            NDBL, DTRANK, DINNER);
    }
    // 5) selective scan + gating (rounds y to tf32 on store)
    {
        dim3 grid(DINNER/16, BATCH);
        scan_kernel<<<grid, 256>>>(dtb, dbl, xc, xz, A_log, D_param, yb);
    }
    // 6) out = y @ out_proj_w^T : M=8192 N=1024 K=2048  (tf32 mma, pre-rounded)
    {
        dim3 grid(DMODEL/128, MROWS/128);
        mma_gemm<0,false,false,false><<<grid, 256, MMA_SMEM_B>>>(
            yb, wb, out, nullptr, MROWS, DMODEL, DINNER,
            DINNER, DINNER, DMODEL);
    }
}

// round 6
// speedup vs baseline: 2.9493x; 1.6509x over previous
#include <cuda_runtime.h>
#include <math.h>
#include <stdint.h>

// Problem constants
#define BATCH   4
#define SEQ     2048
#define DMODEL  1024
#define DINNER  2048
#define DSTATE  16
#define DTRANK  64
#define DCONV   4
#define MROWS   (BATCH*SEQ)          // 8192
#define NXZ     (2*DINNER)           // 4096
#define NDBL    (DTRANK + 2*DSTATE)  // 96
#define NCHUNK  16
#define LCHUNK  (SEQ/NCHUNK)         // 128
#define XPJ_SPLITK 4

// ----------------------------------------------------------------------------
// Scratch (device globals; no runtime allocation allowed)
// ----------------------------------------------------------------------------
__device__ float g_xz [(size_t)MROWS * NXZ];       // in_proj output (x_ssm | z)
__device__ float g_xc [(size_t)MROWS * DINNER];    // conv+silu output
__device__ float g_dbl[(size_t)MROWS * NDBL];      // x_proj output (dt_x | B | C)
__device__ float g_dblp[(size_t)XPJ_SPLITK * MROWS * NDBL]; // split-K partials
__device__ float g_dt [(size_t)MROWS * DINNER];    // softplus(dt)
__device__ float g_y  [(size_t)MROWS * DINNER];    // gated scan output (tf32-rounded)
__device__ float g_xr [(size_t)MROWS * DMODEL];    // tf32-rounded x
__device__ float g_wa [(size_t)NXZ   * DMODEL];    // tf32-rounded in_proj_w
__device__ float g_wb [(size_t)DMODEL* DINNER];    // tf32-rounded out_proj_w
// chunked-scan state: (b, d, n, chunk)
#define SCAN_ST ((size_t)BATCH * DINNER * DSTATE * NCHUNK)
__device__ float g_P [SCAN_ST];
__device__ float g_Q [SCAN_ST];
__device__ float g_HS[SCAN_ST];

// ============================================================================
// mma.sync tf32 helpers (sm_80+ PTX — compiles under compute_103)
// ============================================================================
__device__ __forceinline__ uint32_t f2tf32(float x) {
    uint32_t r;
    asm("cvt.rna.tf32.f32 %0, %1;" : "=r"(r) : "f"(x));
    return r;
}
__device__ __forceinline__ void mma_tf32(float* c, const uint32_t* a, const uint32_t* b) {
    asm volatile(
        "mma.sync.aligned.m16n8k8.row.col.f32.tf32.tf32.f32 "
        "{%0,%1,%2,%3}, {%4,%5,%6,%7}, {%8,%9}, {%0,%1,%2,%3};"
        : "+f"(c[0]), "+f"(c[1]), "+f"(c[2]), "+f"(c[3])
        : "r"(a[0]), "r"(a[1]), "r"(a[2]), "r"(a[3]), "r"(b[0]), "r"(b[1]));
}
__device__ __forceinline__ uint32_t smem_u32(const void* p) {
    uint32_t a;
    asm("{ .reg .u64 t; cvta.to.shared.u64 t, %1; cvt.u32.u64 %0, t; }"
        : "=r"(a) : "l"(p));
    return a;
}
__device__ __forceinline__ void cp_async16(uint32_t dst, const void* src) {
    asm volatile("cp.async.ca.shared.global [%0], [%1], 16;"
                 :: "r"(dst), "l"(src) : "memory");
}
__device__ __forceinline__ void cp_async16z(uint32_t dst, const void* src, bool valid) {
    uint32_t sz = valid ? 16u : 0u;
    asm volatile("cp.async.ca.shared.global [%0], [%1], 16, %2;"
                 :: "r"(dst), "l"(src), "r"(sz) : "memory");
}
#define CP_COMMIT() asm volatile("cp.async.commit_group;" ::: "memory")
#define CP_WAIT(n)  asm volatile("cp.async.wait_group %0;" :: "n"(n) : "memory")

// ============================================================================
// tf32 MMA NT GEMM: C[M,N] = A[M,K] * B[N,K]^T, fp32 accumulate.
// CTA tile 128x128x32, 256 thr (8 warps 2x4), warp tile 64x32.
// EPI: 0 plain, 1 softplus(acc+bias). NGUARD: N-predicate. CVTA/CVTB: in-loop
// tf32 rounding. SPLITK: blockIdx.z selects a K-slice, C offset by z*M*ldc.
// ============================================================================
#define MMA_STRIDE   36
#define MMA_STAGE_F  (128 * MMA_STRIDE)
#define MMA_STAGE_B  (MMA_STAGE_F * 4)
#define MMA_SMEM_B   (4 * MMA_STAGE_B)           // 73728 bytes

template<int EPI, bool NGUARD, bool CVTA, bool CVTB, bool SPLITK>
__global__ void __launch_bounds__(256, 2)
mma_gemm(const float* __restrict__ A, const float* __restrict__ B,
         float* __restrict__ C, const float* __restrict__ bias,
         int M, int N, int K, int lda, int ldb, int ldc)
{
    extern __shared__ float sm[];
    const uint32_t smB = smem_u32(sm);

    if (SPLITK) {
        const int z = blockIdx.z;
        A += (size_t)z * K;
        B += (size_t)z * K;
        C += (size_t)z * M * (size_t)ldc;
    }

    const int tid    = threadIdx.x;
    const int lane   = tid & 31;
    const int wid    = tid >> 5;
    const int warp_m = wid >> 2;
    const int warp_n = wid & 3;
    const int lr     = lane >> 2;
    const int lc     = lane & 3;

    const int rowBase = blockIdx.y * 128;
    const int colBase = blockIdx.x * 128;

    float acc[4][4][4];
#pragma unroll
    for (int mt = 0; mt < 4; ++mt)
#pragma unroll
        for (int nt = 0; nt < 4; ++nt)
#pragma unroll
            for (int i = 0; i < 4; ++i) acc[mt][nt][i] = 0.f;

    const int T = K >> 5;

    auto load_stage = [&](int s, int kt) {
        const int kOff = kt << 5;
        const uint32_t aB = smB + s * MMA_STAGE_B;
        const uint32_t bB = smB + 2 * MMA_STAGE_B + s * MMA_STAGE_B;
#pragma unroll
        for (int i = 0; i < 4; ++i) {
            const int chunk = tid + (i << 8);
            const int row = chunk >> 3;
            const int c4  = chunk & 7;
            const uint32_t so = row * (MMA_STRIDE * 4) + c4 * 16;
            cp_async16(aB + so, &A[(size_t)(rowBase + row) * lda + kOff + c4 * 4]);
            if (NGUARD) {
                const bool ok = (colBase + row) < N;
                const int  br = ok ? (colBase + row) : 0;
                cp_async16z(bB + so, &B[(size_t)br * ldb + kOff + c4 * 4], ok);
            } else {
                cp_async16(bB + so, &B[(size_t)(colBase + row) * ldb + kOff + c4 * 4]);
            }
        }
        CP_COMMIT();
    };

    auto fragA = [&](const float* p) -> uint32_t {
        return CVTA ? f2tf32(*p) : __float_as_uint(*p);
    };
    auto fragB = [&](const float* p) -> uint32_t {
        return CVTB ? f2tf32(*p) : __float_as_uint(*p);
    };

    load_stage(0, 0);

    for (int kt = 0; kt < T; ++kt) {
        const int s = kt & 1;
        if (kt + 1 < T) {
            load_stage(s ^ 1, kt + 1);
            CP_WAIT(1);
        } else {
            CP_WAIT(0);
        }
        __syncthreads();

        const float* As_ = sm + s * MMA_STAGE_F;
        const float* Bs_ = sm + 2 * MMA_STAGE_F + s * MMA_STAGE_F;

#pragma unroll
        for (int kk = 0; kk < 4; ++kk) {
            const int k0 = (kk << 3) + lc;
            uint32_t af[4][4];
#pragma unroll
            for (int mt = 0; mt < 4; ++mt) {
                const float* p = As_ + (warp_m * 64 + mt * 16 + lr) * MMA_STRIDE + k0;
                af[mt][0] = fragA(p);
                af[mt][1] = fragA(p + 8 * MMA_STRIDE);
                af[mt][2] = fragA(p + 4);
                af[mt][3] = fragA(p + 8 * MMA_STRIDE + 4);
            }
            uint32_t bf[4][2];
#pragma unroll
            for (int nt = 0; nt < 4; ++nt) {
                const float* p = Bs_ + (warp_n * 32 + nt * 8 + lr) * MMA_STRIDE + k0;
                bf[nt][0] = fragB(p);
                bf[nt][1] = fragB(p + 4);
            }
#pragma unroll
            for (int mt = 0; mt < 4; ++mt)
#pragma unroll
                for (int nt = 0; nt < 4; ++nt)
                    mma_tf32(acc[mt][nt], af[mt], bf[nt]);
        }
        __syncthreads();
    }

#pragma unroll
    for (int mt = 0; mt < 4; ++mt) {
        const int row = rowBase + warp_m * 64 + mt * 16 + lr;
#pragma unroll
        for (int nt = 0; nt < 4; ++nt) {
            const int col = colBase + warp_n * 32 + nt * 8 + 2 * lc;
            if (NGUARD && col >= N) continue;
            float v[4] = {acc[mt][nt][0], acc[mt][nt][1],
                          acc[mt][nt][2], acc[mt][nt][3]};
            if (EPI == 1) {
                const float b0 = bias[col], b1 = bias[col + 1];
                v[0] += b0; v[1] += b1; v[2] += b0; v[3] += b1;
#pragma unroll
                for (int i = 0; i < 4; ++i)
                    v[i] = fmaxf(v[i], 0.f) + log1pf(__expf(-fabsf(v[i])));
            }
            *reinterpret_cast<float2*>(&C[(size_t)row * ldc + col]) =
                make_float2(v[0], v[1]);
            *reinterpret_cast<float2*>(&C[(size_t)(row + 8) * ldc + col]) =
                make_float2(v[2], v[3]);
        }
    }
}

// ----------------------------------------------------------------------------
// split-K reduce: out[i] = sum_s part[s*stride + i]   (float4 vectorized)
// ----------------------------------------------------------------------------
__global__ void reduce_splitk_kernel(const float4* __restrict__ part,
                                     float4* __restrict__ out, int n4, int stride4)
{
    int i = blockIdx.x * blockDim.x + threadIdx.x;
    if (i < n4) {
        float4 a = part[i];
        float4 b = part[i + stride4];
        float4 c = part[i + 2 * stride4];
        float4 d = part[i + 3 * stride4];
        out[i] = make_float4(a.x + b.x + c.x + d.x, a.y + b.y + c.y + d.y,
                             a.z + b.z + c.z + d.z, a.w + b.w + c.w + d.w);
    }
}

// ----------------------------------------------------------------------------
// Round fp32 array to tf32 (rna)
// ----------------------------------------------------------------------------
__global__ void round_tf32_kernel(const float4* __restrict__ in,
                                  float4* __restrict__ out, int n4)
{
    int i = blockIdx.x * blockDim.x + threadIdx.x;
    if (i < n4) {
        float4 v = in[i];
        v.x = __uint_as_float(f2tf32(v.x));
        v.y = __uint_as_float(f2tf32(v.y));
        v.z = __uint_as_float(f2tf32(v.z));
        v.w = __uint_as_float(f2tf32(v.w));
        out[i] = v;
    }
}

// ----------------------------------------------------------------------------
// Depthwise causal conv (width 4) + SiLU
// ----------------------------------------------------------------------------
__global__ void conv_silu_kernel(const float* __restrict__ xz,
                                 const float* __restrict__ w,
                                 const float* __restrict__ b,
                                 float* __restrict__ xc)
{
    int idx = blockIdx.x * blockDim.x + threadIdx.x;
    int d = idx & (DINNER - 1);
    int m = idx >> 11;
    int l = m & (SEQ - 1);

    float acc = b[d];
#pragma unroll
    for (int j = 0; j < DCONV; ++j) {
        int lj = l - (DCONV - 1) + j;
        if (lj >= 0)
            acc = fmaf(w[d*DCONV + j], xz[(size_t)(m - (DCONV-1) + j) * NXZ + d], acc);
    }
    xc[(size_t)idx] = acc / (1.f + __expf(-acc));
}

// ============================================================================
// Chunked selective scan (3 passes). Lane layout: n = lane&15, 2 channels/warp.
// ============================================================================
// Pass A: per-chunk cumulative product P = prod(dA) and local scan Q (h0=0).
__global__ void __launch_bounds__(256) scan_chunk_kernel(
    const float* __restrict__ dt,  const float* __restrict__ dbl,
    const float* __restrict__ xc,  const float* __restrict__ A_log,
    float* __restrict__ P, float* __restrict__ Q)
{
    const int lane = threadIdx.x & 31;
    const int warp = threadIdx.x >> 5;
    const int n    = lane & 15;
    const int d    = blockIdx.x * 16 + warp * 2 + (lane >> 4);
    const int b    = blockIdx.y;
    const int c    = blockIdx.z;

    const float Ad = -__expf(A_log[d*DSTATE + n]);
    float Pp = 1.f, h = 0.f;

    const int m0 = b * SEQ + c * LCHUNK;
    int m = m0;
    float dtv = dt [(size_t)m*DINNER + d];
    float xv  = xc [(size_t)m*DINNER + d];
    float Bv  = dbl[m*NDBL + DTRANK + n];
    for (int l = 0; l < LCHUNK; ++l) {
        float dtn = 0.f, xn = 0.f, Bn = 0.f;
        if (l + 1 < LCHUNK) {
            const int m1 = m + 1;
            dtn = dt [(size_t)m1*DINNER + d];
            xn  = xc [(size_t)m1*DINNER + d];
            Bn  = dbl[m1*NDBL + DTRANK + n];
        }
        const float dA = __expf(dtv * Ad);
        Pp *= dA;
        h = fmaf(dA, h, dtv * Bv * xv);
        dtv = dtn; xv = xn; Bv = Bn; ++m;
    }
    const size_t idx = ((((size_t)b * DINNER + d) * DSTATE) + n) * NCHUNK + c;
    P[idx] = Pp;
    Q[idx] = h;
}

// Pass B: compose chunk states serially (tiny).
__global__ void __launch_bounds__(256) scan_fix_kernel(
    const float* __restrict__ P, const float* __restrict__ Q,
    float* __restrict__ HS)
{
    const size_t i = (size_t)blockIdx.x * blockDim.x + threadIdx.x;  // (b,d,n)
    const size_t base = i * NCHUNK;
    float h = 0.f;
#pragma unroll
    for (int c = 0; c < NCHUNK; ++c) {
        HS[base + c] = h;
        h = fmaf(P[base + c], h, Q[base + c]);
    }
}

// Pass C: re-scan each chunk from its exact start state, emit gated y.
__global__ void __launch_bounds__(256) scan_y_kernel(
    const float* __restrict__ dt,  const float* __restrict__ dbl,
    const float* __restrict__ xc,  const float* __restrict__ xz,
    const float* __restrict__ A_log, const float* __restrict__ Dp,
    const float* __restrict__ HS, float* __restrict__ y)
{
    const int lane = threadIdx.x & 31;
    const int warp = threadIdx.x >> 5;
    const int n    = lane & 15;
    const int d    = blockIdx.x * 16 + warp * 2 + (lane >> 4);
    const int b    = blockIdx.y;
    const int c    = blockIdx.z;

    const float Ad = -__expf(A_log[d*DSTATE + n]);
    const float Dd = Dp[d];
    float h = HS[((((size_t)b * DINNER + d) * DSTATE) + n) * NCHUNK + c];

    const int m0 = b * SEQ + c * LCHUNK;
    int m = m0;
    float dtv = dt [(size_t)m*DINNER + d];
    float xv  = xc [(size_t)m*DINNER + d];
    float Bv  = dbl[m*NDBL + DTRANK + n];
    float Cv  = dbl[m*NDBL + DTRANK + DSTATE + n];

    for (int l = 0; l < LCHUNK; ++l) {
        float dtn = 0.f, xn = 0.f, Bn = 0.f, Cn = 0.f;
        if (l + 1 < LCHUNK) {
            const int m1 = m + 1;
            dtn = dt [(size_t)m1*DINNER + d];
            xn  = xc [(size_t)m1*DINNER + d];
            Bn  = dbl[m1*NDBL + DTRANK + n];
            Cn  = dbl[m1*NDBL + DTRANK + DSTATE + n];
        }
        const float dA = __expf(dtv * Ad);
        h = fmaf(dA, h, dtv * Bv * xv);

        float p = h * Cv;
        p += __shfl_xor_sync(0xffffffffu, p, 8);
        p += __shfl_xor_sync(0xffffffffu, p, 4);
        p += __shfl_xor_sync(0xffffffffu, p, 2);
        p += __shfl_xor_sync(0xffffffffu, p, 1);

        if (n == 0) {
            const float zv = xz[(size_t)m*NXZ + DINNER + d];
            const float yv = (p + Dd*xv) * (zv / (1.f + __expf(-zv)));
            y[(size_t)m*DINNER + d] = __uint_as_float(f2tf32(yv));
        }
        dtv = dtn; xv = xn; Bv = Bn; Cv = Cn; ++m;
    }
}

// ----------------------------------------------------------------------------
// Launch
// ----------------------------------------------------------------------------
extern "C" void kernel_launch(void* const* d_in, const int* in_sizes, int n_in,
                              void* d_out, int out_size)
{
    const float* x          = (const float*)d_in[0];
    const float* in_proj_w  = (const float*)d_in[1];
    const float* conv_w     = (const float*)d_in[2];
    const float* conv_b     = (const float*)d_in[3];
    const float* x_proj_w   = (const float*)d_in[4];
    const float* dt_proj_w  = (const float*)d_in[5];
    const float* dt_proj_b  = (const float*)d_in[6];
    const float* A_log      = (const float*)d_in[7];
    const float* D_param    = (const float*)d_in[8];
    const float* out_proj_w = (const float*)d_in[9];
    float* out = (float*)d_out;

    float *xz, *xc, *dbl, *dblp, *dtb, *yb, *xr, *wa, *wb, *P, *Q, *HS;
    cudaGetSymbolAddress((void**)&xz,   g_xz);
    cudaGetSymbolAddress((void**)&xc,   g_xc);
    cudaGetSymbolAddress((void**)&dbl,  g_dbl);
    cudaGetSymbolAddress((void**)&dblp, g_dblp);
    cudaGetSymbolAddress((void**)&dtb,  g_dt);
    cudaGetSymbolAddress((void**)&yb,   g_y);
    cudaGetSymbolAddress((void**)&xr,   g_xr);
    cudaGetSymbolAddress((void**)&wa,   g_wa);
    cudaGetSymbolAddress((void**)&wb,   g_wb);
    cudaGetSymbolAddress((void**)&P,    g_P);
    cudaGetSymbolAddress((void**)&Q,    g_Q);
    cudaGetSymbolAddress((void**)&HS,   g_HS);

    cudaFuncSetAttribute((const void*)mma_gemm<0,false,false,false,false>,
                         cudaFuncAttributeMaxDynamicSharedMemorySize, MMA_SMEM_B);
    cudaFuncSetAttribute((const void*)mma_gemm<0,true,true,true,true>,
                         cudaFuncAttributeMaxDynamicSharedMemorySize, MMA_SMEM_B);
    cudaFuncSetAttribute((const void*)mma_gemm<1,false,true,true,false>,
                         cudaFuncAttributeMaxDynamicSharedMemorySize, MMA_SMEM_B);

    // 0) pre-round big GEMM operands to tf32
    {
        int n4;
        n4 = MROWS * DMODEL / 4;
        round_tf32_kernel<<<(n4 + 255)/256, 256>>>((const float4*)x, (float4*)xr, n4);
        n4 = NXZ * DMODEL / 4;
        round_tf32_kernel<<<(n4 + 255)/256, 256>>>((const float4*)in_proj_w, (float4*)wa, n4);
        n4 = DMODEL * DINNER / 4;
        round_tf32_kernel<<<(n4 + 255)/256, 256>>>((const float4*)out_proj_w, (float4*)wb, n4);
    }

    // 1) xz = x @ in_proj_w^T : M=8192 N=4096 K=1024
    {
        dim3 grid(NXZ/128, MROWS/128);
        mma_gemm<0,false,false,false,false><<<grid, 256, MMA_SMEM_B>>>(
            xr, wa, xz, nullptr, MROWS, NXZ, DMODEL, DMODEL, DMODEL, NXZ);
    }
    // 2) depthwise conv + silu
    {
        int total = MROWS * DINNER;
        conv_silu_kernel<<<total/256, 256>>>(xz, conv_w, conv_b, xc);
    }
    // 3) dbl = xc @ x_proj_w^T : M=8192 N=96 K=2048, split-K=4 + reduce
    {
        dim3 grid(1, MROWS/128, XPJ_SPLITK);
        mma_gemm<0,true,true,true,true><<<grid, 256, MMA_SMEM_B>>>(
            xc, x_proj_w, dblp, nullptr, MROWS, NDBL, DINNER/XPJ_SPLITK,
            DINNER, DINNER, NDBL);
        int n4 = MROWS * NDBL / 4;
        reduce_splitk_kernel<<<(n4 + 255)/256, 256>>>(
            (const float4*)dblp, (float4*)dbl, n4, n4);
    }
    // 4) dt = softplus(dbl[:, :64] @ dt_proj_w^T + b) : M=8192 N=2048 K=64
    {
        dim3 grid(DINNER/128, MROWS/128);
        mma_gemm<1,false,true,true,false><<<grid, 256, MMA_SMEM_B>>>(
            dbl, dt_proj_w, dtb, dt_proj_b, MROWS, DINNER, DTRANK,
            NDBL, DTRANK, DINNER);
    }
    // 5) chunked selective scan + gating
    {
        dim3 gridA(DINNER/16, BATCH, NCHUNK);
        scan_chunk_kernel<<<gridA, 256>>>(dtb, dbl, xc, A_log, P, Q);
        int nfix = BATCH * DINNER * DSTATE;           // 131072
        scan_fix_kernel<<<nfix/256, 256>>>(P, Q, HS);
        scan_y_kernel<<<gridA, 256>>>(dtb, dbl, xc, xz, A_log, D_param, HS, yb);
    }
    // 6) out = y @ out_proj_w^T : M=8192 N=1024 K=2048
    {
        dim3 grid(DMODEL/128, MROWS/128);
        mma_gemm<0,false,false,false,false><<<grid, 256, MMA_SMEM_B>>>(
            yb, wb, out, nullptr, MROWS, DMODEL, DINNER,
            DINNER, DINNER, DMODEL);
    }
}

// round 7
// speedup vs baseline: 3.7515x; 1.2720x over previous
#include <cuda_runtime.h>
#include <math.h>
#include <stdint.h>

// Problem constants
#define BATCH   4
#define SEQ     2048
#define DMODEL  1024
#define DINNER  2048
#define DSTATE  16
#define DTRANK  64
#define DCONV   4
#define MROWS   (BATCH*SEQ)          // 8192
#define NXZ     (2*DINNER)           // 4096
#define NDBL    (DTRANK + 2*DSTATE)  // 96
#define NCHUNK  32
#define LCHUNK  (SEQ/NCHUNK)         // 64
#define XPJ_SPLITK 4
#define NBDN    (BATCH*DINNER*DSTATE)    // 131072

// ----------------------------------------------------------------------------
// Scratch (device globals; no runtime allocation allowed)
// ----------------------------------------------------------------------------
__device__ float g_xz [(size_t)MROWS * NXZ];
__device__ float g_xc [(size_t)MROWS * DINNER];
__device__ float g_dbl[(size_t)MROWS * NDBL];
__device__ float g_dblp[(size_t)XPJ_SPLITK * MROWS * NDBL];
__device__ float g_dt [(size_t)MROWS * DINNER];
__device__ float g_y  [(size_t)MROWS * DINNER];
__device__ float g_xr [(size_t)MROWS * DMODEL];
__device__ float g_wa [(size_t)NXZ   * DMODEL];
__device__ float g_wb [(size_t)DMODEL* DINNER];
// chunked-scan state, layout [chunk][b*d*n]
#define SCAN_ST ((size_t)NCHUNK * NBDN)
__device__ float g_P [SCAN_ST];
__device__ float g_Q [SCAN_ST];
__device__ float g_HS[SCAN_ST];

// ============================================================================
// mma.sync tf32 helpers
// ============================================================================
__device__ __forceinline__ uint32_t f2tf32(float x) {
    uint32_t r;
    asm("cvt.rna.tf32.f32 %0, %1;" : "=r"(r) : "f"(x));
    return r;
}
__device__ __forceinline__ void mma_tf32(float* c, const uint32_t* a, const uint32_t* b) {
    asm volatile(
        "mma.sync.aligned.m16n8k8.row.col.f32.tf32.tf32.f32 "
        "{%0,%1,%2,%3}, {%4,%5,%6,%7}, {%8,%9}, {%0,%1,%2,%3};"
        : "+f"(c[0]), "+f"(c[1]), "+f"(c[2]), "+f"(c[3])
        : "r"(a[0]), "r"(a[1]), "r"(a[2]), "r"(a[3]), "r"(b[0]), "r"(b[1]));
}
__device__ __forceinline__ uint32_t smem_u32(const void* p) {
    uint32_t a;
    asm("{ .reg .u64 t; cvta.to.shared.u64 t, %1; cvt.u32.u64 %0, t; }"
        : "=r"(a) : "l"(p));
    return a;
}
__device__ __forceinline__ void cp_async16(uint32_t dst, const void* src) {
    asm volatile("cp.async.ca.shared.global [%0], [%1], 16;"
                 :: "r"(dst), "l"(src) : "memory");
}
__device__ __forceinline__ void cp_async16z(uint32_t dst, const void* src, bool valid) {
    uint32_t sz = valid ? 16u : 0u;
    asm volatile("cp.async.ca.shared.global [%0], [%1], 16, %2;"
                 :: "r"(dst), "l"(src), "r"(sz) : "memory");
}
#define CP_COMMIT() asm volatile("cp.async.commit_group;" ::: "memory")
#define CP_WAIT(n)  asm volatile("cp.async.wait_group %0;" :: "n"(n) : "memory")

// ============================================================================
// tf32 MMA NT GEMM: C[M,N] = A[M,K] * B[N,K]^T, fp32 accumulate.
// CTA tile 128x128x32, 256 thr, warp tile 64x32.
// 3-stage cp.async pipeline, ONE __syncthreads per k-tile.
// ============================================================================
#define MMA_STRIDE   36
#define MMA_STAGE_F  (128 * MMA_STRIDE)
#define MMA_STAGE_B  (MMA_STAGE_F * 4)
#define MMA_SMEM_B   (6 * MMA_STAGE_B)           // 110592 bytes (3 stages x 2)

template<int EPI, bool NGUARD, bool CVTA, bool CVTB, bool SPLITK>
__global__ void __launch_bounds__(256, 2)
mma_gemm(const float* __restrict__ A, const float* __restrict__ B,
         float* __restrict__ C, const float* __restrict__ bias,
         int M, int N, int K, int lda, int ldb, int ldc)
{
    extern __shared__ float sm[];
    const uint32_t smB = smem_u32(sm);

    if (SPLITK) {
        const int z = blockIdx.z;
        A += (size_t)z * K;
        B += (size_t)z * K;
        C += (size_t)z * M * (size_t)ldc;
    }

    const int tid    = threadIdx.x;
    const int lane   = tid & 31;
    const int wid    = tid >> 5;
    const int warp_m = wid >> 2;
    const int warp_n = wid & 3;
    const int lr     = lane >> 2;
    const int lc     = lane & 3;

    const int rowBase = blockIdx.y * 128;
    const int colBase = blockIdx.x * 128;

    float acc[4][4][4];
#pragma unroll
    for (int mt = 0; mt < 4; ++mt)
#pragma unroll
        for (int nt = 0; nt < 4; ++nt)
#pragma unroll
            for (int i = 0; i < 4; ++i) acc[mt][nt][i] = 0.f;

    const int T = K >> 5;

    auto load_stage = [&](int s, int kt) {
        const int kOff = kt << 5;
        const uint32_t aB = smB + s * MMA_STAGE_B;
        const uint32_t bB = smB + 3 * MMA_STAGE_B + s * MMA_STAGE_B;
#pragma unroll
        for (int i = 0; i < 4; ++i) {
            const int chunk = tid + (i << 8);
            const int row = chunk >> 3;
            const int c4  = chunk & 7;
            const uint32_t so = row * (MMA_STRIDE * 4) + c4 * 16;
            cp_async16(aB + so, &A[(size_t)(rowBase + row) * lda + kOff + c4 * 4]);
            if (NGUARD) {
                const bool ok = (colBase + row) < N;
                const int  br = ok ? (colBase + row) : 0;
                cp_async16z(bB + so, &B[(size_t)br * ldb + kOff + c4 * 4], ok);
            } else {
                cp_async16(bB + so, &B[(size_t)(colBase + row) * ldb + kOff + c4 * 4]);
            }
        }
        CP_COMMIT();
    };

    auto fragA = [&](const float* p) -> uint32_t {
        return CVTA ? f2tf32(*p) : __float_as_uint(*p);
    };
    auto fragB = [&](const float* p) -> uint32_t {
        return CVTB ? f2tf32(*p) : __float_as_uint(*p);
    };

    load_stage(0, 0);
    if (T > 1) load_stage(1, 1);

    for (int kt = 0; kt < T; ++kt) {
        const int s = kt - (kt / 3) * 3;          // kt % 3
        if (kt + 1 < T) { CP_WAIT(1); } else { CP_WAIT(0); }
        __syncthreads();
        if (kt + 2 < T) {
            const int s2 = (kt + 2) - ((kt + 2) / 3) * 3;
            load_stage(s2, kt + 2);
        }

        const float* As_ = sm + s * MMA_STAGE_F;
        const float* Bs_ = sm + 3 * MMA_STAGE_F + s * MMA_STAGE_F;

#pragma unroll
        for (int kk = 0; kk < 4; ++kk) {
            const int k0 = (kk << 3) + lc;
            uint32_t af[4][4];
#pragma unroll
            for (int mt = 0; mt < 4; ++mt) {
                const float* p = As_ + (warp_m * 64 + mt * 16 + lr) * MMA_STRIDE + k0;
                af[mt][0] = fragA(p);
                af[mt][1] = fragA(p + 8 * MMA_STRIDE);
                af[mt][2] = fragA(p + 4);
                af[mt][3] = fragA(p + 8 * MMA_STRIDE + 4);
            }
            uint32_t bf[4][2];
#pragma unroll
            for (int nt = 0; nt < 4; ++nt) {
                const float* p = Bs_ + (warp_n * 32 + nt * 8 + lr) * MMA_STRIDE + k0;
                bf[nt][0] = fragB(p);
                bf[nt][1] = fragB(p + 4);
            }
#pragma unroll
            for (int mt = 0; mt < 4; ++mt)
#pragma unroll
                for (int nt = 0; nt < 4; ++nt)
                    mma_tf32(acc[mt][nt], af[mt], bf[nt]);
        }
    }
    __syncthreads();

#pragma unroll
    for (int mt = 0; mt < 4; ++mt) {
        const int row = rowBase + warp_m * 64 + mt * 16 + lr;
#pragma unroll
        for (int nt = 0; nt < 4; ++nt) {
            const int col = colBase + warp_n * 32 + nt * 8 + 2 * lc;
            if (NGUARD && col >= N) continue;
            float v[4] = {acc[mt][nt][0], acc[mt][nt][1],
                          acc[mt][nt][2], acc[mt][nt][3]};
            if (EPI == 1) {
                const float b0 = bias[col], b1 = bias[col + 1];
                v[0] += b0; v[1] += b1; v[2] += b0; v[3] += b1;
#pragma unroll
                for (int i = 0; i < 4; ++i)
                    v[i] = fmaxf(v[i], 0.f) + log1pf(__expf(-fabsf(v[i])));
            }
            *reinterpret_cast<float2*>(&C[(size_t)row * ldc + col]) =
                make_float2(v[0], v[1]);
            *reinterpret_cast<float2*>(&C[(size_t)(row + 8) * ldc + col]) =
                make_float2(v[2], v[3]);
        }
    }
}

// ----------------------------------------------------------------------------
// split-K reduce
// ----------------------------------------------------------------------------
__global__ void reduce_splitk_kernel(const float4* __restrict__ part,
                                     float4* __restrict__ out, int n4, int stride4)
{
    int i = blockIdx.x * blockDim.x + threadIdx.x;
    if (i < n4) {
        float4 a = part[i];
        float4 b = part[i + stride4];
        float4 c = part[i + 2 * stride4];
        float4 d = part[i + 3 * stride4];
        out[i] = make_float4(a.x + b.x + c.x + d.x, a.y + b.y + c.y + d.y,
                             a.z + b.z + c.z + d.z, a.w + b.w + c.w + d.w);
    }
}

// ----------------------------------------------------------------------------
// Round fp32 array to tf32 (rna)
// ----------------------------------------------------------------------------
__global__ void round_tf32_kernel(const float4* __restrict__ in,
                                  float4* __restrict__ out, int n4)
{
    int i = blockIdx.x * blockDim.x + threadIdx.x;
    if (i < n4) {
        float4 v = in[i];
        v.x = __uint_as_float(f2tf32(v.x));
        v.y = __uint_as_float(f2tf32(v.y));
        v.z = __uint_as_float(f2tf32(v.z));
        v.w = __uint_as_float(f2tf32(v.w));
        out[i] = v;
    }
}

// ----------------------------------------------------------------------------
// Depthwise causal conv (width 4) + SiLU — float4 over channels
// ----------------------------------------------------------------------------
__global__ void conv_silu_kernel(const float* __restrict__ xz,
                                 const float* __restrict__ w,
                                 const float* __restrict__ b,
                                 float* __restrict__ xc)
{
    int i = blockIdx.x * blockDim.x + threadIdx.x;   // over MROWS * DINNER/4
    int d4 = (i & 511) << 2;                         // DINNER/4 = 512
    int m  = i >> 9;
    int l  = m & (SEQ - 1);

    float4 wv[4];
#pragma unroll
    for (int c = 0; c < 4; ++c)
        wv[c] = *reinterpret_cast<const float4*>(&w[(d4 + c) * DCONV]);
    float4 acc = *reinterpret_cast<const float4*>(&b[d4]);

#pragma unroll
    for (int j = 0; j < DCONV; ++j) {
        int lj = l - (DCONV - 1) + j;
        if (lj >= 0) {
            float4 xv = *reinterpret_cast<const float4*>(
                &xz[(size_t)(m - (DCONV - 1) + j) * NXZ + d4]);
            acc.x = fmaf(((const float*)&wv[0])[j], xv.x, acc.x);
            acc.y = fmaf(((const float*)&wv[1])[j], xv.y, acc.y);
            acc.z = fmaf(((const float*)&wv[2])[j], xv.z, acc.z);
            acc.w = fmaf(((const float*)&wv[3])[j], xv.w, acc.w);
        }
    }
    acc.x = acc.x / (1.f + __expf(-acc.x));
    acc.y = acc.y / (1.f + __expf(-acc.y));
    acc.z = acc.z / (1.f + __expf(-acc.z));
    acc.w = acc.w / (1.f + __expf(-acc.w));
    *reinterpret_cast<float4*>(&xc[(size_t)m * DINNER + d4]) = acc;
}

// ============================================================================
// Chunked selective scan, smem-staged. Block = 16 channels x 64 steps.
// Lane layout: n = lane&15, dloc = warp*2 + (lane>>4).
// State arrays laid out [chunk][ (b*DINNER+d)*16 + n ].
// ============================================================================
__global__ void __launch_bounds__(256) scan_chunk_kernel(
    const float* __restrict__ dt,  const float* __restrict__ dbl,
    const float* __restrict__ xc,  const float* __restrict__ A_log,
    float* __restrict__ P, float* __restrict__ Q)
{
    __shared__ float s_dt[LCHUNK * 16];
    __shared__ float s_xc[LCHUNK * 16];
    __shared__ float s_B [LCHUNK * 16];

    const int tid  = threadIdx.x;
    const int d0   = blockIdx.x * 16;
    const int b    = blockIdx.y;
    const int c    = blockIdx.z;
    const int m0   = b * SEQ + c * LCHUNK;

    // stage: one float4 per thread per array (64 rows x 16 cols)
    {
        const int trow = tid >> 2;
        const int tc4  = (tid & 3) << 2;
        const size_t gm = (size_t)(m0 + trow);
        *reinterpret_cast<float4*>(&s_dt[trow * 16 + tc4]) =
            *reinterpret_cast<const float4*>(&dt[gm * DINNER + d0 + tc4]);
        *reinterpret_cast<float4*>(&s_xc[trow * 16 + tc4]) =
            *reinterpret_cast<const float4*>(&xc[gm * DINNER + d0 + tc4]);
        *reinterpret_cast<float4*>(&s_B[trow * 16 + tc4]) =
            *reinterpret_cast<const float4*>(&dbl[gm * NDBL + DTRANK + tc4]);
    }
    __syncthreads();

    const int lane = tid & 31;
    const int warp = tid >> 5;
    const int n    = lane & 15;
    const int dloc = warp * 2 + (lane >> 4);
    const int d    = d0 + dloc;

    const float Ad = -__expf(A_log[d * DSTATE + n]);
    float Pp = 1.f, h = 0.f;

#pragma unroll 4
    for (int l = 0; l < LCHUNK; ++l) {
        const float dtv = s_dt[l * 16 + dloc];
        const float xv  = s_xc[l * 16 + dloc];
        const float Bv  = s_B [l * 16 + n];
        const float dA  = __expf(dtv * Ad);
        Pp *= dA;
        h = fmaf(dA, h, dtv * Bv * xv);
    }
    const size_t idx = (size_t)c * NBDN + ((size_t)b * DINNER + d) * DSTATE + n;
    P[idx] = Pp;
    Q[idx] = h;
}

// Pass B: compose chunk states serially (coalesced: [chunk][i] layout).
__global__ void __launch_bounds__(256) scan_fix_kernel(
    const float* __restrict__ P, const float* __restrict__ Q,
    float* __restrict__ HS)
{
    const size_t i = (size_t)blockIdx.x * blockDim.x + threadIdx.x;  // (b,d,n)
    float h = 0.f;
#pragma unroll
    for (int c = 0; c < NCHUNK; ++c) {
        const size_t k = (size_t)c * NBDN + i;
        HS[k] = h;
        h = fmaf(P[k], h, Q[k]);
    }
}

// Pass C: re-scan each chunk from exact start state, emit gated y (tf32).
__global__ void __launch_bounds__(256) scan_y_kernel(
    const float* __restrict__ dt,  const float* __restrict__ dbl,
    const float* __restrict__ xc,  const float* __restrict__ xz,
    const float* __restrict__ A_log, const float* __restrict__ Dp,
    const float* __restrict__ HS, float* __restrict__ y)
{
    __shared__ float s_dt[LCHUNK * 16];
    __shared__ float s_xc[LCHUNK * 16];
    __shared__ float s_B [LCHUNK * 16];
    __shared__ float s_C [LCHUNK * 16];
    __shared__ float s_z [LCHUNK * 16];
    __shared__ float s_y [LCHUNK * 16];

    const int tid  = threadIdx.x;
    const int d0   = blockIdx.x * 16;
    const int b    = blockIdx.y;
    const int c    = blockIdx.z;
    const int m0   = b * SEQ + c * LCHUNK;

    {
        const int trow = tid >> 2;
        const int tc4  = (tid & 3) << 2;
        const size_t gm = (size_t)(m0 + trow);
        *reinterpret_cast<float4*>(&s_dt[trow * 16 + tc4]) =
            *reinterpret_cast<const float4*>(&dt[gm * DINNER + d0 + tc4]);
        *reinterpret_cast<float4*>(&s_xc[trow * 16 + tc4]) =
            *reinterpret_cast<const float4*>(&xc[gm * DINNER + d0 + tc4]);
        *reinterpret_cast<float4*>(&s_B[trow * 16 + tc4]) =
            *reinterpret_cast<const float4*>(&dbl[gm * NDBL + DTRANK + tc4]);
        *reinterpret_cast<float4*>(&s_C[trow * 16 + tc4]) =
            *reinterpret_cast<const float4*>(&dbl[gm * NDBL + DTRANK + DSTATE + tc4]);
        *reinterpret_cast<float4*>(&s_z[trow * 16 + tc4]) =
            *reinterpret_cast<const float4*>(&xz[gm * NXZ + DINNER + d0 + tc4]);
    }
    __syncthreads();

    const int lane = tid & 31;
    const int warp = tid >> 5;
    const int n    = lane & 15;
    const int dloc = warp * 2 + (lane >> 4);
    const int d    = d0 + dloc;

    const float Ad = -__expf(A_log[d * DSTATE + n]);
    const float Dd = Dp[d];
    float h = HS[(size_t)c * NBDN + ((size_t)b * DINNER + d) * DSTATE + n];

#pragma unroll 2
    for (int l = 0; l < LCHUNK; ++l) {
        const float dtv = s_dt[l * 16 + dloc];
        const float xv  = s_xc[l * 16 + dloc];
        const float Bv  = s_B [l * 16 + n];
        const float Cv  = s_C [l * 16 + n];
        const float dA  = __expf(dtv * Ad);
        h = fmaf(dA, h, dtv * Bv * xv);

        float p = h * Cv;
        p += __shfl_xor_sync(0xffffffffu, p, 8);
        p += __shfl_xor_sync(0xffffffffu, p, 4);
        p += __shfl_xor_sync(0xffffffffu, p, 2);
        p += __shfl_xor_sync(0xffffffffu, p, 1);

        if (n == 0) {
            const float zv = s_z[l * 16 + dloc];
            s_y[l * 16 + dloc] = (p + Dd * xv) * (zv / (1.f + __expf(-zv)));
        }
    }
    __syncthreads();

    // coalesced tf32-rounded store
    {
        const int trow = tid >> 2;
        const int tc4  = (tid & 3) << 2;
        float4 v = *reinterpret_cast<const float4*>(&s_y[trow * 16 + tc4]);
        v.x = __uint_as_float(f2tf32(v.x));
        v.y = __uint_as_float(f2tf32(v.y));
        v.z = __uint_as_float(f2tf32(v.z));
        v.w = __uint_as_float(f2tf32(v.w));
        *reinterpret_cast<float4*>(&y[(size_t)(m0 + trow) * DINNER + d0 + tc4]) = v;
    }
}

// ----------------------------------------------------------------------------
// Launch
// ----------------------------------------------------------------------------
extern "C" void kernel_launch(void* const* d_in, const int* in_sizes, int n_in,
                              void* d_out, int out_size)
{
    const float* x          = (const float*)d_in[0];
    const float* in_proj_w  = (const float*)d_in[1];
    const float* conv_w     = (const float*)d_in[2];
    const float* conv_b     = (const float*)d_in[3];
    const float* x_proj_w   = (const float*)d_in[4];
    const float* dt_proj_w  = (const float*)d_in[5];
    const float* dt_proj_b  = (const float*)d_in[6];
    const float* A_log      = (const float*)d_in[7];
    const float* D_param    = (const float*)d_in[8];
    const float* out_proj_w = (const float*)d_in[9];
    float* out = (float*)d_out;

    float *xz, *xc, *dbl, *dblp, *dtb, *yb, *xr, *wa, *wb, *P, *Q, *HS;
    cudaGetSymbolAddress((void**)&xz,   g_xz);
    cudaGetSymbolAddress((void**)&xc,   g_xc);
    cudaGetSymbolAddress((void**)&dbl,  g_dbl);
    cudaGetSymbolAddress((void**)&dblp, g_dblp);
    cudaGetSymbolAddress((void**)&dtb,  g_dt);
    cudaGetSymbolAddress((void**)&yb,   g_y);
    cudaGetSymbolAddress((void**)&xr,   g_xr);
    cudaGetSymbolAddress((void**)&wa,   g_wa);
    cudaGetSymbolAddress((void**)&wb,   g_wb);
    cudaGetSymbolAddress((void**)&P,    g_P);
    cudaGetSymbolAddress((void**)&Q,    g_Q);
    cudaGetSymbolAddress((void**)&HS,   g_HS);

    cudaFuncSetAttribute((const void*)mma_gemm<0,false,false,false,false>,
                         cudaFuncAttributeMaxDynamicSharedMemorySize, MMA_SMEM_B);
    cudaFuncSetAttribute((const void*)mma_gemm<0,true,true,true,true>,
                         cudaFuncAttributeMaxDynamicSharedMemorySize, MMA_SMEM_B);
    cudaFuncSetAttribute((const void*)mma_gemm<1,false,true,true,false>,
                         cudaFuncAttributeMaxDynamicSharedMemorySize, MMA_SMEM_B);

    // 0) pre-round big GEMM operands to tf32
    {
        int n4;
        n4 = MROWS * DMODEL / 4;
        round_tf32_kernel<<<(n4 + 255)/256, 256>>>((const float4*)x, (float4*)xr, n4);
        n4 = NXZ * DMODEL / 4;
        round_tf32_kernel<<<(n4 + 255)/256, 256>>>((const float4*)in_proj_w, (float4*)wa, n4);
        n4 = DMODEL * DINNER / 4;
        round_tf32_kernel<<<(n4 + 255)/256, 256>>>((const float4*)out_proj_w, (float4*)wb, n4);
    }

    // 1) xz = x @ in_proj_w^T : M=8192 N=4096 K=1024
    {
        dim3 grid(NXZ/128, MROWS/128);
        mma_gemm<0,false,false,false,false><<<grid, 256, MMA_SMEM_B>>>(
            xr, wa, xz, nullptr, MROWS, NXZ, DMODEL, DMODEL, DMODEL, NXZ);
    }
    // 2) depthwise conv + silu
    {
        int total = MROWS * DINNER / 4;
        conv_silu_kernel<<<total/256, 256>>>(xz, conv_w, conv_b, xc);
    }
    // 3) dbl = xc @ x_proj_w^T : split-K=4 + reduce
    {
        dim3 grid(1, MROWS/128, XPJ_SPLITK);
        mma_gemm<0,true,true,true,true><<<grid, 256, MMA_SMEM_B>>>(
            xc, x_proj_w, dblp, nullptr, MROWS, NDBL, DINNER/XPJ_SPLITK,
            DINNER, DINNER, NDBL);
        int n4 = MROWS * NDBL / 4;
        reduce_splitk_kernel<<<(n4 + 255)/256, 256>>>(
            (const float4*)dblp, (float4*)dbl, n4, n4);
    }
    // 4) dt = softplus(dbl[:, :64] @ dt_proj_w^T + b)
    {
        dim3 grid(DINNER/128, MROWS/128);
        mma_gemm<1,false,true,true,false><<<grid, 256, MMA_SMEM_B>>>(
            dbl, dt_proj_w, dtb, dt_proj_b, MROWS, DINNER, DTRANK,
            NDBL, DTRANK, DINNER);
    }
    // 5) chunked selective scan + gating (smem-staged)
    {
        dim3 gridA(DINNER/16, BATCH, NCHUNK);
        scan_chunk_kernel<<<gridA, 256>>>(dtb, dbl, xc, A_log, P, Q);
        scan_fix_kernel<<<NBDN/256, 256>>>(P, Q, HS);
        scan_y_kernel<<<gridA, 256>>>(dtb, dbl, xc, xz, A_log, D_param, HS, yb);
    }
    // 6) out = y @ out_proj_w^T : M=8192 N=1024 K=2048
    {
        dim3 grid(DMODEL/128, MROWS/128);
        mma_gemm<0,false,false,false,false><<<grid, 256, MMA_SMEM_B>>>(
            yb, wb, out, nullptr, MROWS, DMODEL, DINNER,
            DINNER, DINNER, DMODEL);
    }
}